// round 1
// baseline (speedup 1.0000x reference)
#include <cuda_runtime.h>
#include <math.h>
#include <stdint.h>

// Problem constants
#define NB   8      // batch
#define TT   512    // tokens
#define DD   1024   // dim
#define TA   256    // even tokens
#define TB2  256    // odd tokens
#define RM   128    // merges
#define TMM  384    // merged tokens = TA + TB2 - RM
#define NH   16
#define HD   64
#define NBINS 16384
#define CAP   4096
#define TARGETN 2048

// ---------------- static device scratch (no allocation allowed) ----------------
__device__ float              g_inorm[NB*TT];
__device__ unsigned int       g_keys[NB*65536];
__device__ unsigned int       g_hist[NB*NBINS];
__device__ int                g_thr[NB];
__device__ int                g_cnt[NB];
__device__ unsigned long long g_gath[NB*CAP];
__device__ int                g_amap[NB*TA];     // a-row -> matched b (or -1)
__device__ int                g_bmap[NB*TB2];    // b-row -> merged row index
__device__ int                g_kept[NB*RM];     // unmatched b rows in ascending order
__device__ float              g_m [NB*TMM*DD];   // merged tokens
__device__ float              g_q [NB*TMM*DD];
__device__ float              g_k [NB*TMM*DD];
__device__ float              g_v [NB*TMM*DD];
__device__ float              g_s [NB*NH*TMM*TMM]; // scores / probs
__device__ float              g_ao[NB*TMM*DD];   // attn @ V (head-merged)
__device__ float              g_pr[NB*TMM*DD];   // final projection

// ---------------- init ----------------
__global__ void k_init() {
    int i = blockIdx.x * blockDim.x + threadIdx.x;
    if (i < NB*NBINS) g_hist[i] = 0u;
    if (i < NB)       g_cnt[i]  = 0;
}

// ---------------- row inverse norms (all 512 rows; even=a, odd=b) ----------------
__global__ void k_norm(const float* __restrict__ x) {
    int row  = blockIdx.x * 8 + (threadIdx.x >> 5);
    if (row >= NB*TT) return;
    int lane = threadIdx.x & 31;
    const float* p = x + (size_t)row * DD;
    float ss = 0.f;
    for (int i = lane; i < DD; i += 32) { float v = p[i]; ss += v*v; }
    #pragma unroll
    for (int o = 16; o; o >>= 1) ss += __shfl_xor_sync(0xffffffffu, ss, o);
    if (lane == 0) g_inorm[row] = 1.0f / fmaxf(sqrtf(ss), 1e-12f);
}

// ---------------- cosine sims -> sortable keys + histogram ----------------
__global__ void k_sim(const float* __restrict__ x) {
    int b  = blockIdx.z;
    int a0 = blockIdx.y * 32;
    int b0 = blockIdx.x * 32;
    int ty = threadIdx.y, tx = threadIdx.x;
    __shared__ float As[32][33], Bs[32][33];
    const float* xb = x + (size_t)b * TT * DD;
    float acc = 0.f;
    for (int k0 = 0; k0 < DD; k0 += 32) {
        As[ty][tx] = xb[(size_t)(2*(a0+ty))   * DD + k0 + tx];
        Bs[ty][tx] = xb[(size_t)(2*(b0+ty)+1) * DD + k0 + tx];
        __syncthreads();
        #pragma unroll
        for (int kk = 0; kk < 32; kk++) acc += As[ty][kk] * Bs[tx][kk];
        __syncthreads();
    }
    float sim = acc * g_inorm[b*TT + 2*(a0+ty)] * g_inorm[b*TT + 2*(b0+tx) + 1];
    unsigned int u = __float_as_uint(sim);
    u = (u & 0x80000000u) ? ~u : (u | 0x80000000u);   // monotone float->uint
    int idx = (a0+ty) * TB2 + (b0+tx);
    g_keys[b*65536 + idx] = u;
    atomicAdd(&g_hist[b*NBINS + (u >> 18)], 1u);
}

// ---------------- per-batch threshold bin: smallest top set with >= TARGETN entries ----------------
__global__ void k_thresh() {
    int b = blockIdx.x, t = threadIdx.x;
    __shared__ unsigned int csum[256];
    unsigned int s = 0;
    for (int j = 0; j < 64; j++) s += g_hist[b*NBINS + (NBINS-1 - (t*64 + j))];
    csum[t] = s;
    __syncthreads();
    if (t == 0) {
        unsigned int acc = 0; int thr = 0;
        int c = 0;
        for (; c < 256; c++) { if (acc + csum[c] >= TARGETN) break; acc += csum[c]; }
        if (c < 256) {
            int binBase = NBINS - 1 - c*64;
            for (int j = 0; j < 64; j++) {
                int bin = binBase - j;
                acc += g_hist[b*NBINS + bin];
                if (acc >= TARGETN) { thr = bin; break; }
            }
        }
        g_thr[b] = thr;
    }
}

// ---------------- gather top entries ----------------
__global__ void k_gather() {
    int i = blockIdx.x * blockDim.x + threadIdx.x;   // 524288 threads
    int b = i >> 16, idx = i & 65535;
    unsigned int key = g_keys[i];
    if ((int)(key >> 18) >= g_thr[b]) {
        int pos = atomicAdd(&g_cnt[b], 1);
        if (pos < CAP)
            g_gath[b*CAP + pos] =
                ((unsigned long long)key << 16) | (unsigned long long)(65535 - idx);
    }
}

// ---------------- bitonic sort (descending) + serial greedy + maps ----------------
__global__ void k_sortgreedy() {
    int b = blockIdx.x, tid = threadIdx.x;
    __shared__ unsigned long long S[CAP];
    __shared__ unsigned long long red[1024];
    __shared__ unsigned char ua[TA], ub[TB2];
    __shared__ int pa[RM], pb[RM];
    __shared__ int sm_cnt;

    int cnt = g_cnt[b];
    int lim = (cnt <= CAP) ? cnt : 0;      // overflow -> full fallback
    for (int i = tid; i < CAP; i += 1024) S[i] = (i < lim) ? g_gath[b*CAP + i] : 0ULL;
    for (int i = tid; i < TA;  i += 1024) { ua[i] = 0; ub[i] = 0; }
    if (tid == 0) sm_cnt = 0;
    __syncthreads();

    // bitonic sort descending over CAP (power of two)
    for (int size = 2; size <= CAP; size <<= 1)
        for (int stride = size >> 1; stride > 0; stride >>= 1) {
            for (int t = tid; t < CAP/2; t += 1024) {
                int pos = 2*t - (t & (stride - 1));
                unsigned long long x0 = S[pos], x1 = S[pos + stride];
                bool up = ((pos & size) == 0);
                if (up ? (x0 < x1) : (x0 > x1)) { S[pos] = x1; S[pos + stride] = x0; }
            }
            __syncthreads();
        }

    if (tid == 0) {
        int m = 0;
        for (int i = 0; i < CAP && m < RM; i++) {
            unsigned long long e = S[i];
            if (!e) break;
            int idx = 65535 - (int)(e & 0xFFFFULL);
            int a = idx >> 8, bb = idx & 255;
            if (!ua[a] && !ub[bb]) { ua[a] = 1; ub[bb] = 1; pa[m] = a; pb[m] = bb; m++; }
        }
        sm_cnt = m;
    }
    __syncthreads();

    // exact fallback: block-wide masked argmax (practically never taken)
    while (sm_cnt < RM) {
        unsigned long long best = 0ULL;
        for (int i = tid; i < 65536; i += 1024) {
            int a = i >> 8, bb = i & 255;
            if (ua[a] || ub[bb]) continue;
            unsigned long long comp =
                ((unsigned long long)g_keys[b*65536 + i] << 16) |
                (unsigned long long)(65535 - i);
            if (comp > best) best = comp;
        }
        red[tid] = best;
        __syncthreads();
        for (int o = 512; o; o >>= 1) {
            if (tid < o) { unsigned long long v = red[tid + o]; if (v > red[tid]) red[tid] = v; }
            __syncthreads();
        }
        if (tid == 0) {
            unsigned long long e = red[0];
            int idx = 65535 - (int)(e & 0xFFFFULL);
            int a = idx >> 8, bb = idx & 255;
            ua[a] = 1; ub[bb] = 1; pa[sm_cnt] = a; pb[sm_cnt] = bb; sm_cnt++;
        }
        __syncthreads();
    }

    if (tid == 0) {
        for (int a = 0; a < TA; a++) g_amap[b*TA + a] = -1;
        for (int i = 0; i < RM; i++) g_amap[b*TA + pa[i]] = pb[i];
        int k = 0;
        for (int bb = 0; bb < TB2; bb++)
            if (!ub[bb]) { g_kept[b*RM + k] = bb; g_bmap[b*TB2 + bb] = TA + k; k++; }
        for (int i = 0; i < RM; i++) g_bmap[b*TB2 + pb[i]] = pa[i];
    }
}

// ---------------- build merged token matrix ----------------
__global__ void k_merge(const float* __restrict__ x) {
    int b = blockIdx.y, row = blockIdx.x, tid = threadIdx.x;  // 256 thr * float4
    const float* xb = x + (size_t)b * TT * DD;
    float4* dst = (float4*)(g_m + ((size_t)b*TMM + row) * DD);
    if (row < TA) {
        const float4* ra = (const float4*)(xb + (size_t)(2*row) * DD);
        int mb = g_amap[b*TA + row];
        if (mb >= 0) {
            const float4* rb = (const float4*)(xb + (size_t)(2*mb + 1) * DD);
            float4 va = ra[tid], vb = rb[tid];
            dst[tid] = make_float4(0.5f*(va.x+vb.x), 0.5f*(va.y+vb.y),
                                   0.5f*(va.z+vb.z), 0.5f*(va.w+vb.w));
        } else dst[tid] = ra[tid];
    } else {
        int bb = g_kept[b*RM + row - TA];
        dst[tid] = ((const float4*)(xb + (size_t)(2*bb + 1) * DD))[tid];
    }
}

// ---------------- generic batched GEMM:  C = alpha * A(MxK) * B(NxK-ish)^T ----------------
// A(m,k) at A[m*sAm + k*sAk], B(n,k) at B[n*sBn + k*sBk], C(m,n) at C[m*sCm + n]
// batch z: zo=z/inner, zi=z%inner with separate outer/inner strides.
__global__ __launch_bounds__(256, 2)
void k_gemm(const float* __restrict__ A, const float* __restrict__ Bm, float* __restrict__ C,
            int M, int N, int K,
            long sAm, long sAk, long sBn, long sBk, long sCm,
            long bAo, long bAi, long bBo, long bBi, long bCo, long bCi,
            int inner, float alpha)
{
    int z = blockIdx.z, zo = z / inner, zi = z % inner;
    A  += (size_t)zo*bAo + (size_t)zi*bAi;
    Bm += (size_t)zo*bBo + (size_t)zi*bBi;
    C  += (size_t)zo*bCo + (size_t)zi*bCi;
    int m0 = blockIdx.y * 128, n0 = blockIdx.x * 128;
    __shared__ float As[8][132], Bs[8][132];
    int tid = threadIdx.x;
    int ty = tid >> 4, tx = tid & 15;
    float acc[8][8];
    #pragma unroll
    for (int i = 0; i < 8; i++)
        #pragma unroll
        for (int j = 0; j < 8; j++) acc[i][j] = 0.f;

    for (int k0 = 0; k0 < K; k0 += 8) {   // K always multiple of 8 here
        if (sAk == 1) {
            #pragma unroll
            for (int i = 0; i < 4; i++) {
                int lin = tid + i*256; int k = lin & 7, m = lin >> 3;
                int gm = m0 + m;
                As[k][m] = (gm < M) ? A[(size_t)gm*sAm + (k0 + k)] : 0.f;
            }
        } else {
            #pragma unroll
            for (int i = 0; i < 4; i++) {
                int lin = tid + i*256; int m = lin & 127, k = lin >> 7;
                int gm = m0 + m;
                As[k][m] = (gm < M) ? A[(size_t)gm + (size_t)(k0 + k)*sAk] : 0.f;
            }
        }
        if (sBk == 1) {
            #pragma unroll
            for (int i = 0; i < 4; i++) {
                int lin = tid + i*256; int k = lin & 7, n = lin >> 3;
                int gn = n0 + n;
                Bs[k][n] = (gn < N) ? Bm[(size_t)gn*sBn + (k0 + k)] : 0.f;
            }
        } else {
            #pragma unroll
            for (int i = 0; i < 4; i++) {
                int lin = tid + i*256; int n = lin & 127, k = lin >> 7;
                int gn = n0 + n;
                Bs[k][n] = (gn < N) ? Bm[(size_t)gn + (size_t)(k0 + k)*sBk] : 0.f;
            }
        }
        __syncthreads();
        #pragma unroll
        for (int kk = 0; kk < 8; kk++) {
            float a[8], bb[8];
            *(float4*)&a[0]  = *(const float4*)&As[kk][ty*8];
            *(float4*)&a[4]  = *(const float4*)&As[kk][ty*8 + 4];
            *(float4*)&bb[0] = *(const float4*)&Bs[kk][tx*8];
            *(float4*)&bb[4] = *(const float4*)&Bs[kk][tx*8 + 4];
            #pragma unroll
            for (int i = 0; i < 8; i++)
                #pragma unroll
                for (int j = 0; j < 8; j++) acc[i][j] += a[i] * bb[j];
        }
        __syncthreads();
    }
    #pragma unroll
    for (int i = 0; i < 8; i++) {
        int gm = m0 + ty*8 + i;
        if (gm >= M) continue;
        #pragma unroll
        for (int j = 0; j < 8; j++) {
            int gn = n0 + tx*8 + j;
            if (gn < N) C[(size_t)gm*sCm + gn] = alpha * acc[i][j];
        }
    }
}

// ---------------- softmax over rows of 384 ----------------
__global__ void k_softmax() {
    int row = blockIdx.x, tid = threadIdx.x;   // 128 threads
    float* p = g_s + (size_t)row * TMM;
    float v0 = p[tid], v1 = p[tid + 128], v2 = p[tid + 256];
    float mx = fmaxf(v0, fmaxf(v1, v2));
    __shared__ float sw[4], sw2[4];
    #pragma unroll
    for (int o = 16; o; o >>= 1) mx = fmaxf(mx, __shfl_xor_sync(0xffffffffu, mx, o));
    if ((tid & 31) == 0) sw[tid >> 5] = mx;
    __syncthreads();
    mx = fmaxf(fmaxf(sw[0], sw[1]), fmaxf(sw[2], sw[3]));
    v0 = expf(v0 - mx); v1 = expf(v1 - mx); v2 = expf(v2 - mx);
    float s = v0 + v1 + v2;
    #pragma unroll
    for (int o = 16; o; o >>= 1) s += __shfl_xor_sync(0xffffffffu, s, o);
    if ((tid & 31) == 0) sw2[tid >> 5] = s;
    __syncthreads();
    s = sw2[0] + sw2[1] + sw2[2] + sw2[3];
    float inv = 1.0f / s;
    p[tid] = v0*inv; p[tid + 128] = v1*inv; p[tid + 256] = v2*inv;
}

// ---------------- unmerge into output ----------------
__global__ void k_unmerge(float* __restrict__ out) {
    int b = blockIdx.y, t = blockIdx.x, tid = threadIdx.x;  // 256 thr * float4
    int src = (t & 1) ? g_bmap[b*TB2 + (t >> 1)] : (t >> 1);
    const float4* s = (const float4*)(g_pr + ((size_t)b*TMM + src) * DD);
    float4* d = (float4*)(out + ((size_t)b*TT + t) * DD);
    d[tid] = s[tid];
}

// ---------------- launch ----------------
extern "C" void kernel_launch(void* const* d_in, const int* in_sizes, int n_in,
                              void* d_out, int out_size) {
    (void)in_sizes; (void)n_in; (void)out_size;
    const float* x  = (const float*)d_in[0];
    const float* Wq = (const float*)d_in[1];
    const float* Wk = (const float*)d_in[2];
    const float* Wv = (const float*)d_in[3];
    const float* Wo = (const float*)d_in[4];
    float* out = (float*)d_out;

    float *pm, *pq, *pk, *pv, *ps, *pao, *ppr;
    cudaGetSymbolAddress((void**)&pm,  g_m);
    cudaGetSymbolAddress((void**)&pq,  g_q);
    cudaGetSymbolAddress((void**)&pk,  g_k);
    cudaGetSymbolAddress((void**)&pv,  g_v);
    cudaGetSymbolAddress((void**)&ps,  g_s);
    cudaGetSymbolAddress((void**)&pao, g_ao);
    cudaGetSymbolAddress((void**)&ppr, g_pr);

    k_init<<<(NB*NBINS + 255)/256, 256>>>();
    k_norm<<<NB*TT/8, 256>>>(x);
    k_sim<<<dim3(8,8,NB), dim3(32,32)>>>(x);
    k_thresh<<<NB, 256>>>();
    k_gather<<<512, 1024>>>();
    k_sortgreedy<<<NB, 1024>>>();
    k_merge<<<dim3(TMM, NB), 256>>>(x);

    const long MD = (long)TMM * DD;       // 393216, per-batch token-matrix stride
    const long SS = (long)TMM * TMM;      // 147456, per-(b,h) score stride

    // Q/K/V projections: (3072 x 1024) = merged (3072 x 1024) @ W^T
    k_gemm<<<dim3(8, 24, 1), 256>>>(pm, Wq, pq, NB*TMM, DD, DD,
        DD,1, DD,1, DD, 0,0, 0,0, 0,0, 1, 1.0f);
    k_gemm<<<dim3(8, 24, 1), 256>>>(pm, Wk, pk, NB*TMM, DD, DD,
        DD,1, DD,1, DD, 0,0, 0,0, 0,0, 1, 1.0f);
    k_gemm<<<dim3(8, 24, 1), 256>>>(pm, Wv, pv, NB*TMM, DD, DD,
        DD,1, DD,1, DD, 0,0, 0,0, 0,0, 1, 1.0f);

    // scores: per (b,h): (384x384) = Q_bh @ K_bh^T / 8
    k_gemm<<<dim3(3, 3, NB*NH), 256>>>(pq, pk, ps, TMM, TMM, HD,
        DD,1, DD,1, TMM,
        MD,(long)HD, MD,(long)HD, (long)NH*SS,SS, NH, 0.125f);

    k_softmax<<<NB*NH*TMM, 128>>>();

    // attn @ V: per (b,h): (384x64) = P @ V_bh   (B accessed transposed: sBn=1, sBk=1024)
    k_gemm<<<dim3(1, 3, NB*NH), 256>>>(ps, pv, pao, TMM, HD, TMM,
        TMM,1, 1,DD, DD,
        (long)NH*SS,SS, MD,(long)HD, MD,(long)HD, NH, 1.0f);

    // output projection
    k_gemm<<<dim3(8, 24, 1), 256>>>(pao, Wo, ppr, NB*TMM, DD, DD,
        DD,1, DD,1, DD, 0,0, 0,0, 0,0, 1, 1.0f);

    k_unmerge<<<dim3(TT, NB), 256>>>(out);
}

// round 3
// speedup vs baseline: 1.8311x; 1.8311x over previous
#include <cuda_runtime.h>
#include <cuda_bf16.h>
#include <math.h>
#include <stdint.h>

// Problem constants
#define NB   8      // batch
#define TT   512    // tokens
#define DD   1024   // dim
#define TA   256    // even tokens
#define TB2  256    // odd tokens
#define RM   128    // merges
#define TMM  384    // merged tokens = TA + TB2 - RM
#define NH   16
#define HD   64
#define NBINS 16384
#define CAP   4096
#define TARGETN 2048

// ---------------- static device scratch (no allocation allowed) ----------------
__device__ float              g_inorm[NB*TT];
__device__ unsigned int       g_keys[NB*65536];
__device__ unsigned int       g_hist[NB*NBINS];
__device__ int                g_thr[NB];
__device__ int                g_cnt[NB];
__device__ unsigned long long g_gath[NB*CAP];
__device__ int                g_amap[NB*TA];
__device__ int                g_bmap[NB*TB2];
__device__ int                g_kept[NB*RM];
__device__ float              g_m [NB*TMM*DD];
__device__ float              g_q [NB*TMM*DD];
__device__ float              g_k [NB*TMM*DD];
__device__ float              g_v [NB*TMM*DD];
__device__ float              g_s [NB*NH*TMM*TMM];
__device__ float              g_ao[NB*TMM*DD];
__device__ float              g_pr[NB*TMM*DD];

// ---------------- init ----------------
__global__ void k_init() {
    int i = blockIdx.x * blockDim.x + threadIdx.x;
    if (i < NB*NBINS) g_hist[i] = 0u;
    if (i < NB)       g_cnt[i]  = 0;
}

// ---------------- row inverse norms ----------------
__global__ void k_norm(const float* __restrict__ x) {
    int row  = blockIdx.x * 8 + (threadIdx.x >> 5);
    if (row >= NB*TT) return;
    int lane = threadIdx.x & 31;
    const float* p = x + (size_t)row * DD;
    float ss = 0.f;
    for (int i = lane; i < DD; i += 32) { float v = p[i]; ss += v*v; }
    #pragma unroll
    for (int o = 16; o; o >>= 1) ss += __shfl_xor_sync(0xffffffffu, ss, o);
    if (lane == 0) g_inorm[row] = 1.0f / fmaxf(sqrtf(ss), 1e-12f);
}

// ---------------- cosine sims -> sortable keys + histogram (fp32, exact order) ----------------
__global__ void k_sim(const float* __restrict__ x) {
    int b  = blockIdx.z;
    int a0 = blockIdx.y * 32;
    int b0 = blockIdx.x * 32;
    int ty = threadIdx.y, tx = threadIdx.x;
    __shared__ float As[32][33], Bs[32][33];
    const float* xb = x + (size_t)b * TT * DD;
    float acc = 0.f;
    for (int k0 = 0; k0 < DD; k0 += 32) {
        As[ty][tx] = xb[(size_t)(2*(a0+ty))   * DD + k0 + tx];
        Bs[ty][tx] = xb[(size_t)(2*(b0+ty)+1) * DD + k0 + tx];
        __syncthreads();
        #pragma unroll
        for (int kk = 0; kk < 32; kk++) acc += As[ty][kk] * Bs[tx][kk];
        __syncthreads();
    }
    float sim = acc * g_inorm[b*TT + 2*(a0+ty)] * g_inorm[b*TT + 2*(b0+tx) + 1];
    unsigned int u = __float_as_uint(sim);
    u = (u & 0x80000000u) ? ~u : (u | 0x80000000u);
    int idx = (a0+ty) * TB2 + (b0+tx);
    g_keys[b*65536 + idx] = u;
    atomicAdd(&g_hist[b*NBINS + (u >> 18)], 1u);
}

// ---------------- per-batch threshold bin ----------------
__global__ void k_thresh() {
    int b = blockIdx.x, t = threadIdx.x;
    __shared__ unsigned int csum[256];
    unsigned int s = 0;
    for (int j = 0; j < 64; j++) s += g_hist[b*NBINS + (NBINS-1 - (t*64 + j))];
    csum[t] = s;
    __syncthreads();
    if (t == 0) {
        unsigned int acc = 0; int thr = 0;
        int c = 0;
        for (; c < 256; c++) { if (acc + csum[c] >= TARGETN) break; acc += csum[c]; }
        if (c < 256) {
            int binBase = NBINS - 1 - c*64;
            for (int j = 0; j < 64; j++) {
                int bin = binBase - j;
                acc += g_hist[b*NBINS + bin];
                if (acc >= TARGETN) { thr = bin; break; }
            }
        }
        g_thr[b] = thr;
    }
}

// ---------------- gather top entries ----------------
__global__ void k_gather() {
    int i = blockIdx.x * blockDim.x + threadIdx.x;
    int b = i >> 16, idx = i & 65535;
    unsigned int key = g_keys[i];
    if ((int)(key >> 18) >= g_thr[b]) {
        int pos = atomicAdd(&g_cnt[b], 1);
        if (pos < CAP)
            g_gath[b*CAP + pos] =
                ((unsigned long long)key << 16) | (unsigned long long)(65535 - idx);
    }
}

// ---------------- bitonic sort + serial greedy + maps ----------------
__global__ void k_sortgreedy() {
    int b = blockIdx.x, tid = threadIdx.x;
    __shared__ unsigned long long S[CAP];
    __shared__ unsigned long long red[1024];
    __shared__ unsigned char ua[TA], ub[TB2];
    __shared__ int pa[RM], pb[RM];
    __shared__ int sm_cnt;

    int cnt = g_cnt[b];
    int lim = (cnt <= CAP) ? cnt : 0;
    for (int i = tid; i < CAP; i += 1024) S[i] = (i < lim) ? g_gath[b*CAP + i] : 0ULL;
    for (int i = tid; i < TA;  i += 1024) { ua[i] = 0; ub[i] = 0; }
    if (tid == 0) sm_cnt = 0;
    __syncthreads();

    for (int size = 2; size <= CAP; size <<= 1)
        for (int stride = size >> 1; stride > 0; stride >>= 1) {
            for (int t = tid; t < CAP/2; t += 1024) {
                int pos = 2*t - (t & (stride - 1));
                unsigned long long x0 = S[pos], x1 = S[pos + stride];
                bool up = ((pos & size) == 0);
                if (up ? (x0 < x1) : (x0 > x1)) { S[pos] = x1; S[pos + stride] = x0; }
            }
            __syncthreads();
        }

    if (tid == 0) {
        int m = 0;
        for (int i = 0; i < CAP && m < RM; i++) {
            unsigned long long e = S[i];
            if (!e) break;
            int idx = 65535 - (int)(e & 0xFFFFULL);
            int a = idx >> 8, bb = idx & 255;
            if (!ua[a] && !ub[bb]) { ua[a] = 1; ub[bb] = 1; pa[m] = a; pb[m] = bb; m++; }
        }
        sm_cnt = m;
    }
    __syncthreads();

    while (sm_cnt < RM) {
        unsigned long long best = 0ULL;
        for (int i = tid; i < 65536; i += 1024) {
            int a = i >> 8, bb = i & 255;
            if (ua[a] || ub[bb]) continue;
            unsigned long long comp =
                ((unsigned long long)g_keys[b*65536 + i] << 16) |
                (unsigned long long)(65535 - i);
            if (comp > best) best = comp;
        }
        red[tid] = best;
        __syncthreads();
        for (int o = 512; o; o >>= 1) {
            if (tid < o) { unsigned long long v = red[tid + o]; if (v > red[tid]) red[tid] = v; }
            __syncthreads();
        }
        if (tid == 0) {
            unsigned long long e = red[0];
            int idx = 65535 - (int)(e & 0xFFFFULL);
            int a = idx >> 8, bb = idx & 255;
            ua[a] = 1; ub[bb] = 1; pa[sm_cnt] = a; pb[sm_cnt] = bb; sm_cnt++;
        }
        __syncthreads();
    }

    if (tid == 0) {
        for (int a = 0; a < TA; a++) g_amap[b*TA + a] = -1;
        for (int i = 0; i < RM; i++) g_amap[b*TA + pa[i]] = pb[i];
        int k = 0;
        for (int bb = 0; bb < TB2; bb++)
            if (!ub[bb]) { g_kept[b*RM + k] = bb; g_bmap[b*TB2 + bb] = TA + k; k++; }
        for (int i = 0; i < RM; i++) g_bmap[b*TB2 + pb[i]] = pa[i];
    }
}

// ---------------- build merged token matrix ----------------
__global__ void k_merge(const float* __restrict__ x) {
    int b = blockIdx.y, row = blockIdx.x, tid = threadIdx.x;
    const float* xb = x + (size_t)b * TT * DD;
    float4* dst = (float4*)(g_m + ((size_t)b*TMM + row) * DD);
    if (row < TA) {
        const float4* ra = (const float4*)(xb + (size_t)(2*row) * DD);
        int mb = g_amap[b*TA + row];
        if (mb >= 0) {
            const float4* rb = (const float4*)(xb + (size_t)(2*mb + 1) * DD);
            float4 va = ra[tid], vb = rb[tid];
            dst[tid] = make_float4(0.5f*(va.x+vb.x), 0.5f*(va.y+vb.y),
                                   0.5f*(va.z+vb.z), 0.5f*(va.w+vb.w));
        } else dst[tid] = ra[tid];
    } else {
        int bb = g_kept[b*RM + row - TA];
        dst[tid] = ((const float4*)(xb + (size_t)(2*bb + 1) * DD))[tid];
    }
}

// =======================================================================
//  Tensor-core GEMM:  C = alpha * A(MxK) @ B(NxK)^T   via bf16x3 split
//  A row-k contiguous (sAk==1 always).  B either k-contiguous (sBk==1)
//  or n-contiguous (sBn==1, sBk=stride).  fp32 in/out, ~fp32 accuracy.
// =======================================================================
#define BM 128
#define BN 128
#define BK 32
#define LDS_K 40   // BK + 8 pad (bf16 elems) -> conflict-free fragment loads

__device__ __forceinline__ unsigned pk2(__nv_bfloat16 a, __nv_bfloat16 b) {
    return (unsigned)__bfloat16_as_ushort(a) | ((unsigned)__bfloat16_as_ushort(b) << 16);
}
__device__ __forceinline__ void split2(float v, __nv_bfloat16& h, __nv_bfloat16& l) {
    h = __float2bfloat16_rn(v);
    l = __float2bfloat16_rn(v - __bfloat162float(h));
}

#define MMA_BF16(d, a, b) \
    asm volatile("mma.sync.aligned.m16n8k16.row.col.f32.bf16.bf16.f32 " \
                 "{%0,%1,%2,%3},{%4,%5,%6,%7},{%8,%9},{%0,%1,%2,%3};" \
                 : "+f"(d[0]), "+f"(d[1]), "+f"(d[2]), "+f"(d[3]) \
                 : "r"(a[0]), "r"(a[1]), "r"(a[2]), "r"(a[3]), "r"(b[0]), "r"(b[1]))

__global__ __launch_bounds__(256)
void k_mma(const float* __restrict__ A, const float* __restrict__ B, float* __restrict__ C,
           int M, int N, int K,
           long sAm, long sBn, long sBk, long sCm,
           long bAo, long bAi, long bBo, long bBi, long bCo, long bCi,
           int inner, float alpha)
{
    int z = blockIdx.z, zo = z / inner, zi = z % inner;
    A += (size_t)zo*bAo + (size_t)zi*bAi;
    B += (size_t)zo*bBo + (size_t)zi*bBi;
    C += (size_t)zo*bCo + (size_t)zi*bCi;
    int m0 = blockIdx.y * BM, n0 = blockIdx.x * BN;

    __shared__ unsigned short Ah[BM][LDS_K], Al[BM][LDS_K];
    __shared__ unsigned short Bh[BN][LDS_K], Bl[BN][LDS_K];

    int tid  = threadIdx.x;
    int warp = tid >> 5, lane = tid & 31;
    int g    = lane >> 2, tg = lane & 3;
    int wm   = (warp >> 1) * 32;   // warp m-offset (4 warps over M)
    int wn   = (warp & 1) * 64;    // warp n-offset (2 warps over N)

    float acc[2][8][4];
    #pragma unroll
    for (int i = 0; i < 2; i++)
        #pragma unroll
        for (int j = 0; j < 8; j++)
            #pragma unroll
            for (int c = 0; c < 4; c++) acc[i][j][c] = 0.f;

    for (int k0 = 0; k0 < K; k0 += BK) {
        // ---- fill A tile (always k-contiguous) ----
        #pragma unroll
        for (int i = 0; i < 4; i++) {
            int idx = tid + i*256;           // 1024 float4 slots
            int row = idx >> 3, kq = (idx & 7) * 4;
            int gm = m0 + row;
            float4 v = make_float4(0.f,0.f,0.f,0.f);
            if (gm < M) v = *(const float4*)(A + (size_t)gm*sAm + k0 + kq);
            __nv_bfloat16 h0,h1,h2,h3,l0,l1,l2,l3;
            split2(v.x,h0,l0); split2(v.y,h1,l1); split2(v.z,h2,l2); split2(v.w,h3,l3);
            *(uint2*)&Ah[row][kq] = make_uint2(pk2(h0,h1), pk2(h2,h3));
            *(uint2*)&Al[row][kq] = make_uint2(pk2(l0,l1), pk2(l2,l3));
        }
        // ---- fill B tile ----
        if (sBk == 1) {
            #pragma unroll
            for (int i = 0; i < 4; i++) {
                int idx = tid + i*256;
                int row = idx >> 3, kq = (idx & 7) * 4;
                int gn = n0 + row;
                float4 v = make_float4(0.f,0.f,0.f,0.f);
                if (gn < N) v = *(const float4*)(B + (size_t)gn*sBn + k0 + kq);
                __nv_bfloat16 h0,h1,h2,h3,l0,l1,l2,l3;
                split2(v.x,h0,l0); split2(v.y,h1,l1); split2(v.z,h2,l2); split2(v.w,h3,l3);
                *(uint2*)&Bh[row][kq] = make_uint2(pk2(h0,h1), pk2(h2,h3));
                *(uint2*)&Bl[row][kq] = make_uint2(pk2(l0,l1), pk2(l2,l3));
            }
        } else {  // sBn == 1: n-contiguous, k strided (V in P@V)
            #pragma unroll
            for (int i = 0; i < 4; i++) {
                int idx = tid + i*256;
                int n  = idx & 127, k4 = (idx >> 7) * 4;
                int gn = n0 + n;
                float v0=0.f,v1=0.f,v2=0.f,v3=0.f;
                if (gn < N) {
                    const float* p = B + gn + (size_t)(k0 + k4)*sBk;
                    v0 = p[0]; v1 = p[sBk]; v2 = p[2*sBk]; v3 = p[3*sBk];
                }
                __nv_bfloat16 h0,h1,h2,h3,l0,l1,l2,l3;
                split2(v0,h0,l0); split2(v1,h1,l1); split2(v2,h2,l2); split2(v3,h3,l3);
                *(uint2*)&Bh[n][k4] = make_uint2(pk2(h0,h1), pk2(h2,h3));
                *(uint2*)&Bl[n][k4] = make_uint2(pk2(l0,l1), pk2(l2,l3));
            }
        }
        __syncthreads();

        // ---- two k-chunks of 16 ----
        #pragma unroll
        for (int kc = 0; kc < 2; kc++) {
            unsigned ah[2][4], al[2][4], bh[8][2], bl[8][2];
            int kb = kc*16 + 2*tg;
            #pragma unroll
            for (int mt = 0; mt < 2; mt++) {
                int r0 = wm + mt*16 + g;
                ah[mt][0] = *(unsigned*)&Ah[r0  ][kb];
                ah[mt][1] = *(unsigned*)&Ah[r0+8][kb];
                ah[mt][2] = *(unsigned*)&Ah[r0  ][kb+8];
                ah[mt][3] = *(unsigned*)&Ah[r0+8][kb+8];
                al[mt][0] = *(unsigned*)&Al[r0  ][kb];
                al[mt][1] = *(unsigned*)&Al[r0+8][kb];
                al[mt][2] = *(unsigned*)&Al[r0  ][kb+8];
                al[mt][3] = *(unsigned*)&Al[r0+8][kb+8];
            }
            #pragma unroll
            for (int nt = 0; nt < 8; nt++) {
                int c0 = wn + nt*8 + g;
                bh[nt][0] = *(unsigned*)&Bh[c0][kb];
                bh[nt][1] = *(unsigned*)&Bh[c0][kb+8];
                bl[nt][0] = *(unsigned*)&Bl[c0][kb];
                bl[nt][1] = *(unsigned*)&Bl[c0][kb+8];
            }
            #pragma unroll
            for (int mt = 0; mt < 2; mt++)
                #pragma unroll
                for (int nt = 0; nt < 8; nt++) {
                    MMA_BF16(acc[mt][nt], ah[mt], bh[nt]);
                    MMA_BF16(acc[mt][nt], ah[mt], bl[nt]);
                    MMA_BF16(acc[mt][nt], al[mt], bh[nt]);
                }
        }
        __syncthreads();
    }

    // ---- store ----
    #pragma unroll
    for (int mt = 0; mt < 2; mt++) {
        #pragma unroll
        for (int nt = 0; nt < 8; nt++) {
            int gm = m0 + wm + mt*16 + g;
            int gn = n0 + wn + nt*8 + 2*tg;
            if (gn < N) {
                if (gm < M) {
                    float2 v = make_float2(alpha*acc[mt][nt][0], alpha*acc[mt][nt][1]);
                    *(float2*)(C + (size_t)gm*sCm + gn) = v;
                }
                if (gm + 8 < M) {
                    float2 v = make_float2(alpha*acc[mt][nt][2], alpha*acc[mt][nt][3]);
                    *(float2*)(C + (size_t)(gm+8)*sCm + gn) = v;
                }
            }
        }
    }
}

// ---------------- softmax over rows of 384 ----------------
__global__ void k_softmax() {
    int row = blockIdx.x, tid = threadIdx.x;
    float* p = g_s + (size_t)row * TMM;
    float v0 = p[tid], v1 = p[tid + 128], v2 = p[tid + 256];
    float mx = fmaxf(v0, fmaxf(v1, v2));
    __shared__ float sw[4], sw2[4];
    #pragma unroll
    for (int o = 16; o; o >>= 1) mx = fmaxf(mx, __shfl_xor_sync(0xffffffffu, mx, o));
    if ((tid & 31) == 0) sw[tid >> 5] = mx;
    __syncthreads();
    mx = fmaxf(fmaxf(sw[0], sw[1]), fmaxf(sw[2], sw[3]));
    v0 = expf(v0 - mx); v1 = expf(v1 - mx); v2 = expf(v2 - mx);
    float s = v0 + v1 + v2;
    #pragma unroll
    for (int o = 16; o; o >>= 1) s += __shfl_xor_sync(0xffffffffu, s, o);
    if ((tid & 31) == 0) sw2[tid >> 5] = s;
    __syncthreads();
    s = sw2[0] + sw2[1] + sw2[2] + sw2[3];
    float inv = 1.0f / s;
    p[tid] = v0*inv; p[tid + 128] = v1*inv; p[tid + 256] = v2*inv;
}

// ---------------- unmerge into output ----------------
__global__ void k_unmerge(float* __restrict__ out) {
    int b = blockIdx.y, t = blockIdx.x, tid = threadIdx.x;
    int src = (t & 1) ? g_bmap[b*TB2 + (t >> 1)] : (t >> 1);
    const float4* s = (const float4*)(g_pr + ((size_t)b*TMM + src) * DD);
    float4* d = (float4*)(out + ((size_t)b*TT + t) * DD);
    d[tid] = s[tid];
}

// ---------------- launch ----------------
extern "C" void kernel_launch(void* const* d_in, const int* in_sizes, int n_in,
                              void* d_out, int out_size) {
    (void)in_sizes; (void)n_in; (void)out_size;
    const float* x  = (const float*)d_in[0];
    const float* Wq = (const float*)d_in[1];
    const float* Wk = (const float*)d_in[2];
    const float* Wv = (const float*)d_in[3];
    const float* Wo = (const float*)d_in[4];
    float* out = (float*)d_out;

    float *pm, *pq, *pk, *pv, *ps, *pao, *ppr;
    cudaGetSymbolAddress((void**)&pm,  g_m);
    cudaGetSymbolAddress((void**)&pq,  g_q);
    cudaGetSymbolAddress((void**)&pk,  g_k);
    cudaGetSymbolAddress((void**)&pv,  g_v);
    cudaGetSymbolAddress((void**)&ps,  g_s);
    cudaGetSymbolAddress((void**)&pao, g_ao);
    cudaGetSymbolAddress((void**)&ppr, g_pr);

    k_init<<<(NB*NBINS + 255)/256, 256>>>();
    k_norm<<<NB*TT/8, 256>>>(x);
    k_sim<<<dim3(8,8,NB), dim3(32,32)>>>(x);
    k_thresh<<<NB, 256>>>();
    k_gather<<<512, 1024>>>();
    k_sortgreedy<<<NB, 1024>>>();
    k_merge<<<dim3(TMM, NB), 256>>>(x);

    const long MD = (long)TMM * DD;       // per-batch token-matrix stride
    const long SS = (long)TMM * TMM;      // per-(b,h) score stride

    // Q/K/V projections: (3072 x 1024) = merged @ W^T
    k_mma<<<dim3(8, 24, 1), 256>>>(pm, Wq, pq, NB*TMM, DD, DD,
        DD, DD, 1, DD, 0,0, 0,0, 0,0, 1, 1.0f);
    k_mma<<<dim3(8, 24, 1), 256>>>(pm, Wk, pk, NB*TMM, DD, DD,
        DD, DD, 1, DD, 0,0, 0,0, 0,0, 1, 1.0f);
    k_mma<<<dim3(8, 24, 1), 256>>>(pm, Wv, pv, NB*TMM, DD, DD,
        DD, DD, 1, DD, 0,0, 0,0, 0,0, 1, 1.0f);

    // scores: per (b,h): (384x384) = Q_bh @ K_bh^T / 8
    k_mma<<<dim3(3, 3, NB*NH), 256>>>(pq, pk, ps, TMM, TMM, HD,
        DD, DD, 1, TMM,
        MD, (long)HD, MD, (long)HD, (long)NH*SS, SS, NH, 0.125f);

    k_softmax<<<NB*NH*TMM, 128>>>();

    // attn @ V: per (b,h): (384x64) = P @ V_bh  (B n-contiguous, k-strided)
    k_mma<<<dim3(1, 3, NB*NH), 256>>>(ps, pv, pao, TMM, HD, TMM,
        TMM, 1, DD, DD,
        (long)NH*SS, SS, MD, (long)HD, MD, (long)HD, NH, 1.0f);

    // output projection
    k_mma<<<dim3(8, 24, 1), 256>>>(pao, Wo, ppr, NB*TMM, DD, DD,
        DD, DD, 1, DD, 0,0, 0,0, 0,0, 1, 1.0f);

    k_unmerge<<<dim3(TT, NB), 256>>>(out);
}

// round 6
// speedup vs baseline: 2.8283x; 1.5446x over previous
#include <cuda_runtime.h>
#include <cuda_bf16.h>
#include <math.h>
#include <stdint.h>

// Problem constants
#define NB   8
#define TT   512
#define DD   1024
#define TA   256
#define TB2  256
#define RM   128
#define TMM  384
#define NH   16
#define HD   64
#define NBINS 16384
#define CAP   4096
#define TARGETN 2048
#define SS   (TMM*TMM)

// ---------------- static device scratch ----------------
__device__ float              g_inorm[NB*TT];
__device__ unsigned int       g_keys[NB*65536];
__device__ unsigned int       g_hist[NB*NBINS];
__device__ int                g_thr[NB];
__device__ int                g_cnt[NB];
__device__ unsigned long long g_gath[NB*CAP];
__device__ int                g_amap[NB*TA];
__device__ int                g_bmap[NB*TB2];
__device__ int                g_kept[NB*RM];
// pre-split bf16 (hi/lo) operand buffers
__device__ unsigned short g_mh [NB*TMM*DD],   g_ml [NB*TMM*DD];    // merged tokens
__device__ unsigned short g_wch[3*DD*DD],     g_wcl[3*DD*DD];      // Wq|Wk|Wv stacked
__device__ unsigned short g_woh[DD*DD],       g_wol[DD*DD];        // Wo
__device__ unsigned short g_qkh[NB*TMM*3*DD], g_qkl[NB*TMM*3*DD];  // Q|K|V
__device__ float          g_s  [NB*NH*SS];                          // scores (fp32)
__device__ unsigned short g_ph [NB*NH*SS],    g_pl [NB*NH*SS];     // softmax probs
__device__ unsigned short g_aoh[NB*TMM*DD],   g_aol[NB*TMM*DD];    // attn out
__device__ float          g_pr [NB*TMM*DD];                         // final proj

// ---------------- helpers ----------------
__device__ __forceinline__ unsigned pk2u(unsigned short a, unsigned short b) {
    return (unsigned)a | ((unsigned)b << 16);
}
__device__ __forceinline__ void split2u(float v, unsigned short& h, unsigned short& l) {
    __nv_bfloat16 hb = __float2bfloat16_rn(v);
    __nv_bfloat16 lb = __float2bfloat16_rn(v - __bfloat162float(hb));
    h = __bfloat16_as_ushort(hb);
    l = __bfloat16_as_ushort(lb);
}

// ---------------- init ----------------
__global__ void k_init() {
    int i = blockIdx.x * blockDim.x + threadIdx.x;
    if (i < NB*NBINS) g_hist[i] = 0u;
    if (i < NB)       g_cnt[i]  = 0;
}

// ---------------- row inverse norms ----------------
__global__ void k_norm(const float* __restrict__ x) {
    int row  = blockIdx.x * 8 + (threadIdx.x >> 5);
    if (row >= NB*TT) return;
    int lane = threadIdx.x & 31;
    const float* p = x + (size_t)row * DD;
    float ss = 0.f;
    for (int i = lane; i < DD; i += 32) { float v = p[i]; ss += v*v; }
    #pragma unroll
    for (int o = 16; o; o >>= 1) ss += __shfl_xor_sync(0xffffffffu, ss, o);
    if (lane == 0) g_inorm[row] = 1.0f / fmaxf(sqrtf(ss), 1e-12f);
}

// ---------------- weight convert/split: Wq|Wk|Wv stacked + Wo ----------------
__global__ void k_cvtW(const float* __restrict__ Wq, const float* __restrict__ Wk,
                       const float* __restrict__ Wv, const float* __restrict__ Wo) {
    int t = blockIdx.x * blockDim.x + threadIdx.x;     // 1,048,576 float4 slots
    int which = t >> 18, rem = t & 262143;
    const float* src = (which == 0) ? Wq : (which == 1) ? Wk : (which == 2) ? Wv : Wo;
    float4 v = *(const float4*)(src + (size_t)rem * 4);
    unsigned short h0,h1,h2,h3,l0,l1,l2,l3;
    split2u(v.x,h0,l0); split2u(v.y,h1,l1); split2u(v.z,h2,l2); split2u(v.w,h3,l3);
    uint2 hh = make_uint2(pk2u(h0,h1), pk2u(h2,h3));
    uint2 ll = make_uint2(pk2u(l0,l1), pk2u(l2,l3));
    if (which < 3) {
        *(uint2*)(g_wch + (size_t)t*4) = hh;
        *(uint2*)(g_wcl + (size_t)t*4) = ll;
    } else {
        *(uint2*)(g_woh + (size_t)rem*4) = hh;
        *(uint2*)(g_wol + (size_t)rem*4) = ll;
    }
}

// ---------------- cosine sims (fp32 register-tiled 4x4) ----------------
__global__ void k_sim(const float* __restrict__ x) {
    int b  = blockIdx.z;
    int a0 = blockIdx.y * 64;
    int b0 = blockIdx.x * 64;
    int tid = threadIdx.x;
    int tx = tid & 15, ty = tid >> 4;
    __shared__ float As[16][68], Bs[16][68];
    const float* xb = x + (size_t)b * TT * DD;
    float acc[4][4];
    #pragma unroll
    for (int i = 0; i < 4; i++)
        #pragma unroll
        for (int j = 0; j < 4; j++) acc[i][j] = 0.f;

    int frow = tid >> 2, fq = tid & 3;
    for (int k0 = 0; k0 < DD; k0 += 16) {
        float4 va = *(const float4*)(xb + (size_t)(2*(a0+frow))   * DD + k0 + fq*4);
        float4 vb = *(const float4*)(xb + (size_t)(2*(b0+frow)+1) * DD + k0 + fq*4);
        As[fq*4+0][frow]=va.x; As[fq*4+1][frow]=va.y; As[fq*4+2][frow]=va.z; As[fq*4+3][frow]=va.w;
        Bs[fq*4+0][frow]=vb.x; Bs[fq*4+1][frow]=vb.y; Bs[fq*4+2][frow]=vb.z; Bs[fq*4+3][frow]=vb.w;
        __syncthreads();
        #pragma unroll
        for (int kk = 0; kk < 16; kk++) {
            float4 a4 = *(const float4*)&As[kk][ty*4];
            float4 b4 = *(const float4*)&Bs[kk][tx*4];
            float a[4] = {a4.x,a4.y,a4.z,a4.w}, bb[4] = {b4.x,b4.y,b4.z,b4.w};
            #pragma unroll
            for (int i = 0; i < 4; i++)
                #pragma unroll
                for (int j = 0; j < 4; j++) acc[i][j] += a[i]*bb[j];
        }
        __syncthreads();
    }
    float ina[4], inb[4];
    #pragma unroll
    for (int i = 0; i < 4; i++) ina[i] = g_inorm[b*TT + 2*(a0+ty*4+i)];
    #pragma unroll
    for (int j = 0; j < 4; j++) inb[j] = g_inorm[b*TT + 2*(b0+tx*4+j) + 1];
    #pragma unroll
    for (int i = 0; i < 4; i++)
        #pragma unroll
        for (int j = 0; j < 4; j++) {
            float sim = acc[i][j] * ina[i] * inb[j];
            unsigned u = __float_as_uint(sim);
            u = (u & 0x80000000u) ? ~u : (u | 0x80000000u);
            int idx = (a0+ty*4+i) * TB2 + (b0+tx*4+j);
            g_keys[b*65536 + idx] = u;
            atomicAdd(&g_hist[b*NBINS + (u >> 18)], 1u);
        }
}

// ---------------- per-batch threshold bin ----------------
__global__ void k_thresh() {
    int b = blockIdx.x, t = threadIdx.x;
    __shared__ unsigned int csum[256];
    unsigned int s = 0;
    for (int j = 0; j < 64; j++) s += g_hist[b*NBINS + (NBINS-1 - (t*64 + j))];
    csum[t] = s;
    __syncthreads();
    if (t == 0) {
        unsigned int acc = 0; int thr = 0;
        int c = 0;
        for (; c < 256; c++) { if (acc + csum[c] >= TARGETN) break; acc += csum[c]; }
        if (c < 256) {
            int binBase = NBINS - 1 - c*64;
            for (int j = 0; j < 64; j++) {
                int bin = binBase - j;
                acc += g_hist[b*NBINS + bin];
                if (acc >= TARGETN) { thr = bin; break; }
            }
        }
        g_thr[b] = thr;
    }
}

// ---------------- gather top entries ----------------
__global__ void k_gather() {
    int i = blockIdx.x * blockDim.x + threadIdx.x;
    int b = i >> 16, idx = i & 65535;
    unsigned int key = g_keys[i];
    if ((int)(key >> 18) >= g_thr[b]) {
        int pos = atomicAdd(&g_cnt[b], 1);
        if (pos < CAP)
            g_gath[b*CAP + pos] =
                ((unsigned long long)key << 16) | (unsigned long long)(65535 - idx);
    }
}

// ---------------- bitonic sort + serial greedy + maps ----------------
__global__ void k_sortgreedy() {
    int b = blockIdx.x, tid = threadIdx.x;
    __shared__ unsigned long long S[CAP];
    __shared__ unsigned long long red[1024];
    __shared__ unsigned char ua[TA], ub[TB2];
    __shared__ int pa[RM], pb[RM];
    __shared__ int sm_cnt;

    int cnt = g_cnt[b];
    int lim = (cnt <= CAP) ? cnt : 0;
    for (int i = tid; i < CAP; i += 1024) S[i] = (i < lim) ? g_gath[b*CAP + i] : 0ULL;
    for (int i = tid; i < TA;  i += 1024) { ua[i] = 0; ub[i] = 0; }
    if (tid == 0) sm_cnt = 0;
    __syncthreads();

    for (int size = 2; size <= CAP; size <<= 1)
        for (int stride = size >> 1; stride > 0; stride >>= 1) {
            for (int t = tid; t < CAP/2; t += 1024) {
                int pos = 2*t - (t & (stride - 1));
                unsigned long long x0 = S[pos], x1 = S[pos + stride];
                bool up = ((pos & size) == 0);
                if (up ? (x0 < x1) : (x0 > x1)) { S[pos] = x1; S[pos + stride] = x0; }
            }
            __syncthreads();
        }

    if (tid == 0) {
        int m = 0;
        for (int i = 0; i < CAP && m < RM; i++) {
            unsigned long long e = S[i];
            if (!e) break;
            int idx = 65535 - (int)(e & 0xFFFFULL);
            int a = idx >> 8, bb = idx & 255;
            if (!ua[a] && !ub[bb]) { ua[a] = 1; ub[bb] = 1; pa[m] = a; pb[m] = bb; m++; }
        }
        sm_cnt = m;
    }
    __syncthreads();

    while (sm_cnt < RM) {
        unsigned long long best = 0ULL;
        for (int i = tid; i < 65536; i += 1024) {
            int a = i >> 8, bb = i & 255;
            if (ua[a] || ub[bb]) continue;
            unsigned long long comp =
                ((unsigned long long)g_keys[b*65536 + i] << 16) |
                (unsigned long long)(65535 - i);
            if (comp > best) best = comp;
        }
        red[tid] = best;
        __syncthreads();
        for (int o = 512; o; o >>= 1) {
            if (tid < o) { unsigned long long v = red[tid + o]; if (v > red[tid]) red[tid] = v; }
            __syncthreads();
        }
        if (tid == 0) {
            unsigned long long e = red[0];
            int idx = 65535 - (int)(e & 0xFFFFULL);
            int a = idx >> 8, bb = idx & 255;
            ua[a] = 1; ub[bb] = 1; pa[sm_cnt] = a; pb[sm_cnt] = bb; sm_cnt++;
        }
        __syncthreads();
    }

    if (tid == 0) {
        for (int a = 0; a < TA; a++) g_amap[b*TA + a] = -1;
        for (int i = 0; i < RM; i++) g_amap[b*TA + pa[i]] = pb[i];
        int k = 0;
        for (int bb = 0; bb < TB2; bb++)
            if (!ub[bb]) { g_kept[b*RM + k] = bb; g_bmap[b*TB2 + bb] = TA + k; k++; }
        for (int i = 0; i < RM; i++) g_bmap[b*TB2 + pb[i]] = pa[i];
    }
}

// ---------------- build merged tokens (writes bf16 hi/lo) ----------------
__global__ void k_merge(const float* __restrict__ x) {
    int b = blockIdx.y, row = blockIdx.x, tid = threadIdx.x;
    const float* xb = x + (size_t)b * TT * DD;
    float4 v;
    if (row < TA) {
        const float4* ra = (const float4*)(xb + (size_t)(2*row) * DD);
        int mb = g_amap[b*TA + row];
        if (mb >= 0) {
            const float4* rb = (const float4*)(xb + (size_t)(2*mb + 1) * DD);
            float4 va = ra[tid], vb = rb[tid];
            v = make_float4(0.5f*(va.x+vb.x), 0.5f*(va.y+vb.y),
                            0.5f*(va.z+vb.z), 0.5f*(va.w+vb.w));
        } else v = ra[tid];
    } else {
        int bb = g_kept[b*RM + row - TA];
        v = ((const float4*)(xb + (size_t)(2*bb + 1) * DD))[tid];
    }
    unsigned short h0,h1,h2,h3,l0,l1,l2,l3;
    split2u(v.x,h0,l0); split2u(v.y,h1,l1); split2u(v.z,h2,l2); split2u(v.w,h3,l3);
    size_t e = ((size_t)b*TMM + row) * DD + tid*4;
    *(uint2*)(g_mh + e) = make_uint2(pk2u(h0,h1), pk2u(h2,h3));
    *(uint2*)(g_ml + e) = make_uint2(pk2u(l0,l1), pk2u(l2,l3));
}

// =======================================================================
//  Pre-split bf16x3 tensor-core GEMM, cp.async double-buffered.
//  C = alpha * A(MxK) @ B(NxK)^T.  512 threads, BM=BN=128, BK=32.
// =======================================================================
#define BK 32
#define SROW 40                       // smem row stride (bf16 elems), conflict-free
#define ARR_ELEMS (128*SROW)          // 5120
#define STAGE_ELEMS (4*ARR_ELEMS)     // 20480
#define SMEM_BYTES (2*STAGE_ELEMS*2)  // 81920

#define MMA_BF16(d, a, b) \
    asm volatile("mma.sync.aligned.m16n8k16.row.col.f32.bf16.bf16.f32 " \
                 "{%0,%1,%2,%3},{%4,%5,%6,%7},{%8,%9},{%0,%1,%2,%3};" \
                 : "+f"(d[0]), "+f"(d[1]), "+f"(d[2]), "+f"(d[3]) \
                 : "r"(a[0]), "r"(a[1]), "r"(a[2]), "r"(a[3]), "r"(b[0]), "r"(b[1]))

__device__ __forceinline__ void cp16(unsigned short* dst, const unsigned short* src) {
    unsigned s = (unsigned)__cvta_generic_to_shared(dst);
    asm volatile("cp.async.cg.shared.global [%0], [%1], 16;\n" :: "r"(s), "l"(src));
}

__global__ __launch_bounds__(512)
void k_mma2(const unsigned short* __restrict__ Ahg, const unsigned short* __restrict__ Alg,
            const unsigned short* __restrict__ Bhg, const unsigned short* __restrict__ Blg,
            float* __restrict__ Cf, unsigned short* __restrict__ Ch, unsigned short* __restrict__ Cl,
            int M, int N, int K,
            long sAm, long sBn, long sBk, long sCm,
            long bAo, long bAi, long bBo, long bBi, long bCo, long bCi,
            int inner, float alpha, int modeB)
{
    extern __shared__ unsigned short sm_[];
    int z = blockIdx.z, zo = z / inner, zi = z % inner;
    Ahg += (size_t)zo*bAo + (size_t)zi*bAi;
    Alg += (size_t)zo*bAo + (size_t)zi*bAi;
    Bhg += (size_t)zo*bBo + (size_t)zi*bBi;
    Blg += (size_t)zo*bBo + (size_t)zi*bBi;
    size_t coff = (size_t)zo*bCo + (size_t)zi*bCi;
    int m0 = blockIdx.y * 128, n0 = blockIdx.x * 128;

    int tid  = threadIdx.x;
    int warp = tid >> 5, lane = tid & 31;
    int g    = lane >> 2, tg = lane & 3;
    int wm   = (warp >> 2) * 32;   // 4 warps over M
    int wn   = (warp &  3) * 32;   // 4 warps over N

    float acc[2][4][4];
    #pragma unroll
    for (int i = 0; i < 2; i++)
        #pragma unroll
        for (int j = 0; j < 4; j++)
            #pragma unroll
            for (int c = 0; c < 4; c++) acc[i][j][c] = 0.f;

    const int ntiles = K / BK;

    // ---- fill (stage, k0) ----
    auto fill = [&](int stage, int k0) {
        unsigned short* sb = sm_ + stage * STAGE_ELEMS;
        if (!modeB) {
            #pragma unroll
            for (int i = 0; i < 4; i++) {
                int c = tid + i*512;                 // 2048 16B chunks
                int arr = c >> 9, rem = c & 511;
                int row = rem >> 2, q = rem & 3;
                const unsigned short* src;
                if      (arr == 0) src = Ahg + (size_t)(m0+row)*sAm + k0 + q*8;
                else if (arr == 1) src = Alg + (size_t)(m0+row)*sAm + k0 + q*8;
                else if (arr == 2) src = Bhg + (size_t)(n0+row)*sBn + k0 + q*8;
                else               src = Blg + (size_t)(n0+row)*sBn + k0 + q*8;
                cp16(sb + arr*ARR_ELEMS + row*SROW + q*8, src);
            }
        } else {
            #pragma unroll
            for (int i = 0; i < 2; i++) {            // A via cp.async
                int c = tid + i*512;
                int arr = c >> 9, rem = c & 511;
                int row = rem >> 2, q = rem & 3;
                const unsigned short* src = (arr ? Alg : Ahg) + (size_t)(m0+row)*sAm + k0 + q*8;
                cp16(sb + arr*ARR_ELEMS + row*SROW + q*8, src);
            }
            #pragma unroll
            for (int i = 0; i < 8; i++) {            // B strided gathers (n-contig)
                int s = tid + i*512;                 // 4096 elems per array
                int n = s & 127, kk = s >> 7;
                unsigned short vh = 0, vl = 0;
                int gn = n0 + n;
                if (gn < N) {
                    size_t off = (size_t)gn + (size_t)(k0 + kk) * sBk;
                    vh = Bhg[off]; vl = Blg[off];
                }
                sb[2*ARR_ELEMS + n*SROW + kk] = vh;
                sb[3*ARR_ELEMS + n*SROW + kk] = vl;
            }
        }
    };

    fill(0, 0);
    asm volatile("cp.async.commit_group;\n");

    for (int t = 0; t < ntiles; t++) {
        if (t + 1 < ntiles) fill((t+1) & 1, (t+1)*BK);
        asm volatile("cp.async.commit_group;\n");
        asm volatile("cp.async.wait_group 1;\n");
        __syncthreads();

        const unsigned short* sb = sm_ + (t & 1) * STAGE_ELEMS;
        const unsigned short* Ahs = sb;
        const unsigned short* Als = sb + ARR_ELEMS;
        const unsigned short* Bhs = sb + 2*ARR_ELEMS;
        const unsigned short* Bls = sb + 3*ARR_ELEMS;

        #pragma unroll
        for (int kc = 0; kc < 2; kc++) {
            int kb = kc*16 + 2*tg;
            unsigned ah[2][4], al[2][4], bh[4][2], bl[4][2];
            #pragma unroll
            for (int mt = 0; mt < 2; mt++) {
                int r0 = wm + mt*16 + g;
                ah[mt][0] = *(const unsigned*)(Ahs + r0*SROW + kb);
                ah[mt][1] = *(const unsigned*)(Ahs + (r0+8)*SROW + kb);
                ah[mt][2] = *(const unsigned*)(Ahs + r0*SROW + kb + 8);
                ah[mt][3] = *(const unsigned*)(Ahs + (r0+8)*SROW + kb + 8);
                al[mt][0] = *(const unsigned*)(Als + r0*SROW + kb);
                al[mt][1] = *(const unsigned*)(Als + (r0+8)*SROW + kb);
                al[mt][2] = *(const unsigned*)(Als + r0*SROW + kb + 8);
                al[mt][3] = *(const unsigned*)(Als + (r0+8)*SROW + kb + 8);
            }
            #pragma unroll
            for (int nt = 0; nt < 4; nt++) {
                int c0 = wn + nt*8 + g;
                bh[nt][0] = *(const unsigned*)(Bhs + c0*SROW + kb);
                bh[nt][1] = *(const unsigned*)(Bhs + c0*SROW + kb + 8);
                bl[nt][0] = *(const unsigned*)(Bls + c0*SROW + kb);
                bl[nt][1] = *(const unsigned*)(Bls + c0*SROW + kb + 8);
            }
            // 3 passes: dependency chains on same acc are 8 MMAs apart
            #pragma unroll
            for (int mt = 0; mt < 2; mt++)
                #pragma unroll
                for (int nt = 0; nt < 4; nt++) MMA_BF16(acc[mt][nt], ah[mt], bh[nt]);
            #pragma unroll
            for (int mt = 0; mt < 2; mt++)
                #pragma unroll
                for (int nt = 0; nt < 4; nt++) MMA_BF16(acc[mt][nt], ah[mt], bl[nt]);
            #pragma unroll
            for (int mt = 0; mt < 2; mt++)
                #pragma unroll
                for (int nt = 0; nt < 4; nt++) MMA_BF16(acc[mt][nt], al[mt], bh[nt]);
        }
        __syncthreads();
    }

    // ---- epilogue ----
    #pragma unroll
    for (int mt = 0; mt < 2; mt++) {
        #pragma unroll
        for (int nt = 0; nt < 4; nt++) {
            int gm = m0 + wm + mt*16 + g;
            int gn = n0 + wn + nt*8 + 2*tg;
            if (gn >= N) continue;
            float v0 = alpha*acc[mt][nt][0], v1 = alpha*acc[mt][nt][1];
            float v2 = alpha*acc[mt][nt][2], v3 = alpha*acc[mt][nt][3];
            if (Cf) {
                if (gm < M)     *(float2*)(Cf + coff + (size_t)gm*sCm + gn)     = make_float2(v0, v1);
                if (gm + 8 < M) *(float2*)(Cf + coff + (size_t)(gm+8)*sCm + gn) = make_float2(v2, v3);
            }
            if (Ch) {
                unsigned short h0,h1,h2,h3,l0,l1,l2,l3;
                split2u(v0,h0,l0); split2u(v1,h1,l1); split2u(v2,h2,l2); split2u(v3,h3,l3);
                if (gm < M) {
                    *(unsigned*)(Ch + coff + (size_t)gm*sCm + gn) = pk2u(h0,h1);
                    *(unsigned*)(Cl + coff + (size_t)gm*sCm + gn) = pk2u(l0,l1);
                }
                if (gm + 8 < M) {
                    *(unsigned*)(Ch + coff + (size_t)(gm+8)*sCm + gn) = pk2u(h2,h3);
                    *(unsigned*)(Cl + coff + (size_t)(gm+8)*sCm + gn) = pk2u(l2,l3);
                }
            }
        }
    }
}

// ---------------- softmax over rows of 384 (reads f32, writes bf16 hi/lo) ----------------
__global__ void k_softmax() {
    int row = blockIdx.x, tid = threadIdx.x;
    float* p = g_s + (size_t)row * TMM;
    float v0 = p[tid], v1 = p[tid + 128], v2 = p[tid + 256];
    float mx = fmaxf(v0, fmaxf(v1, v2));
    __shared__ float sw[4], sw2[4];
    #pragma unroll
    for (int o = 16; o; o >>= 1) mx = fmaxf(mx, __shfl_xor_sync(0xffffffffu, mx, o));
    if ((tid & 31) == 0) sw[tid >> 5] = mx;
    __syncthreads();
    mx = fmaxf(fmaxf(sw[0], sw[1]), fmaxf(sw[2], sw[3]));
    v0 = expf(v0 - mx); v1 = expf(v1 - mx); v2 = expf(v2 - mx);
    float s = v0 + v1 + v2;
    #pragma unroll
    for (int o = 16; o; o >>= 1) s += __shfl_xor_sync(0xffffffffu, s, o);
    if ((tid & 31) == 0) sw2[tid >> 5] = s;
    __syncthreads();
    s = sw2[0] + sw2[1] + sw2[2] + sw2[3];
    float inv = 1.0f / s;
    size_t base = (size_t)row * TMM;
    unsigned short h, l;
    split2u(v0*inv, h, l); g_ph[base + tid]       = h; g_pl[base + tid]       = l;
    split2u(v1*inv, h, l); g_ph[base + tid + 128] = h; g_pl[base + tid + 128] = l;
    split2u(v2*inv, h, l); g_ph[base + tid + 256] = h; g_pl[base + tid + 256] = l;
}

// ---------------- unmerge into output ----------------
__global__ void k_unmerge(float* __restrict__ out) {
    int b = blockIdx.y, t = blockIdx.x, tid = threadIdx.x;
    int src = (t & 1) ? g_bmap[b*TB2 + (t >> 1)] : (t >> 1);
    const float4* s = (const float4*)(g_pr + ((size_t)b*TMM + src) * DD);
    float4* d = (float4*)(out + ((size_t)b*TT + t) * DD);
    d[tid] = s[tid];
}

// ---------------- launch ----------------
extern "C" void kernel_launch(void* const* d_in, const int* in_sizes, int n_in,
                              void* d_out, int out_size) {
    (void)in_sizes; (void)n_in; (void)out_size;
    const float* x  = (const float*)d_in[0];
    const float* Wq = (const float*)d_in[1];
    const float* Wk = (const float*)d_in[2];
    const float* Wv = (const float*)d_in[3];
    const float* Wo = (const float*)d_in[4];
    float* out = (float*)d_out;

    static int smem_set = 0;
    if (!smem_set) {
        cudaFuncSetAttribute(k_mma2, cudaFuncAttributeMaxDynamicSharedMemorySize, SMEM_BYTES);
        smem_set = 1;
    }

    unsigned short *pmh,*pml,*pwch,*pwcl,*pwoh,*pwol,*pqkh,*pqkl,*pph,*ppl,*paoh,*paol;
    float *ps, *ppr;
    cudaGetSymbolAddress((void**)&pmh,  g_mh);  cudaGetSymbolAddress((void**)&pml,  g_ml);
    cudaGetSymbolAddress((void**)&pwch, g_wch); cudaGetSymbolAddress((void**)&pwcl, g_wcl);
    cudaGetSymbolAddress((void**)&pwoh, g_woh); cudaGetSymbolAddress((void**)&pwol, g_wol);
    cudaGetSymbolAddress((void**)&pqkh, g_qkh); cudaGetSymbolAddress((void**)&pqkl, g_qkl);
    cudaGetSymbolAddress((void**)&pph,  g_ph);  cudaGetSymbolAddress((void**)&ppl,  g_pl);
    cudaGetSymbolAddress((void**)&paoh, g_aoh); cudaGetSymbolAddress((void**)&paol, g_aol);
    cudaGetSymbolAddress((void**)&ps,   g_s);   cudaGetSymbolAddress((void**)&ppr,  g_pr);

    k_init<<<(NB*NBINS + 255)/256, 256>>>();
    k_norm<<<NB*TT/8, 256>>>(x);
    k_cvtW<<<4096, 256>>>(Wq, Wk, Wv, Wo);
    k_sim<<<dim3(4,4,NB), 256>>>(x);
    k_thresh<<<NB, 256>>>();
    k_gather<<<512, 1024>>>();
    k_sortgreedy<<<NB, 1024>>>();
    k_merge<<<dim3(TMM, NB), 256>>>(x);

    const long MD3 = (long)TMM * 3 * DD;   // per-batch Q|K|V row-block stride

    // fused QKV projection: (3072 x 3072) = merged(3072x1024) @ Wcat^T -> split bf16
    k_mma2<<<dim3(24, 24, 1), 512, SMEM_BYTES>>>(
        pmh, pml, pwch, pwcl, nullptr, pqkh, pqkl,
        NB*TMM, 3*DD, DD,
        DD, DD, 0, 3*DD,
        0,0, 0,0, 0,0, 1, 1.0f, 0);

    // scores: per (b,h): (384x384) = Q_bh @ K_bh^T / 8  -> fp32
    k_mma2<<<dim3(3, 3, NB*NH), 512, SMEM_BYTES>>>(
        pqkh, pqkl, pqkh + DD, pqkl + DD, ps, nullptr, nullptr,
        TMM, TMM, HD,
        3*DD, 3*DD, 0, TMM,
        MD3, (long)HD, MD3, (long)HD, (long)NH*SS, (long)SS, NH, 0.125f, 0);

    k_softmax<<<NB*NH*TMM, 128>>>();

    // attn @ V: per (b,h): (384x64) = P @ V_bh   (B = V^T, n-contig strided)
    k_mma2<<<dim3(1, 3, NB*NH), 512, SMEM_BYTES>>>(
        pph, ppl, pqkh + 2*DD, pqkl + 2*DD, nullptr, paoh, paol,
        TMM, HD, TMM,
        TMM, 0, 3*DD, DD,
        (long)NH*SS, (long)SS, MD3, (long)HD, (long)TMM*DD, (long)HD, NH, 1.0f, 1);

    // output projection -> fp32
    k_mma2<<<dim3(8, 24, 1), 512, SMEM_BYTES>>>(
        paoh, paol, pwoh, pwol, ppr, nullptr, nullptr,
        NB*TMM, DD, DD,
        DD, DD, 0, DD,
        0,0, 0,0, 0,0, 1, 1.0f, 0);

    k_unmerge<<<dim3(TT, NB), 256>>>(out);
}

// round 10
// speedup vs baseline: 2.9021x; 1.0261x over previous
#include <cuda_runtime.h>
#include <cuda_bf16.h>
#include <math.h>
#include <stdint.h>

// Problem constants
#define NB   8
#define TT   512
#define DD   1024
#define TA   256
#define TB2  256
#define RM   128
#define TMM  384
#define NH   16
#define HD   64
#define NBINS 16384
#define CAP   4096
#define TARGETN 2048
#define SS   (TMM*TMM)

// ---------------- static device scratch ----------------
__device__ float              g_inorm[NB*TT];
__device__ unsigned int       g_keys[NB*65536];
__device__ unsigned int       g_hist[NB*NBINS];
__device__ int                g_thr[NB];
__device__ int                g_cnt[NB];
__device__ unsigned long long g_gath[NB*CAP];
__device__ int                g_amap[NB*TA];
__device__ int                g_bmap[NB*TB2];
__device__ int                g_kept[NB*RM];
// pre-split bf16 (hi/lo) operand buffers
__device__ unsigned short g_mh [NB*TMM*DD],   g_ml [NB*TMM*DD];
__device__ unsigned short g_wch[3*DD*DD],     g_wcl[3*DD*DD];
__device__ unsigned short g_woh[DD*DD],       g_wol[DD*DD];
__device__ unsigned short g_qkh[NB*TMM*3*DD], g_qkl[NB*TMM*3*DD];
__device__ float          g_s  [NB*NH*SS];
__device__ unsigned short g_ph [NB*NH*SS],    g_pl [NB*NH*SS];
__device__ unsigned short g_aoh[NB*TMM*DD],   g_aol[NB*TMM*DD];
__device__ float          g_pr [NB*TMM*DD];

// ---------------- helpers ----------------
__device__ __forceinline__ unsigned pk2u(unsigned short a, unsigned short b) {
    return (unsigned)a | ((unsigned)b << 16);
}
__device__ __forceinline__ void split2u(float v, unsigned short& h, unsigned short& l) {
    __nv_bfloat16 hb = __float2bfloat16_rn(v);
    __nv_bfloat16 lb = __float2bfloat16_rn(v - __bfloat162float(hb));
    h = __bfloat16_as_ushort(hb);
    l = __bfloat16_as_ushort(lb);
}

// ---------------- init ----------------
__global__ void k_init() {
    int i = blockIdx.x * blockDim.x + threadIdx.x;
    if (i < NB*NBINS) g_hist[i] = 0u;
    if (i < NB)       g_cnt[i]  = 0;
}

// ---------------- row inverse norms ----------------
__global__ void k_norm(const float* __restrict__ x) {
    int row  = blockIdx.x * 8 + (threadIdx.x >> 5);
    if (row >= NB*TT) return;
    int lane = threadIdx.x & 31;
    const float* p = x + (size_t)row * DD;
    float ss = 0.f;
    for (int i = lane; i < DD; i += 32) { float v = p[i]; ss += v*v; }
    #pragma unroll
    for (int o = 16; o; o >>= 1) ss += __shfl_xor_sync(0xffffffffu, ss, o);
    if (lane == 0) g_inorm[row] = 1.0f / fmaxf(sqrtf(ss), 1e-12f);
}

// ---------------- weight convert/split ----------------
__global__ void k_cvtW(const float* __restrict__ Wq, const float* __restrict__ Wk,
                       const float* __restrict__ Wv, const float* __restrict__ Wo) {
    int t = blockIdx.x * blockDim.x + threadIdx.x;
    int which = t >> 18, rem = t & 262143;
    const float* src = (which == 0) ? Wq : (which == 1) ? Wk : (which == 2) ? Wv : Wo;
    float4 v = *(const float4*)(src + (size_t)rem * 4);
    unsigned short h0,h1,h2,h3,l0,l1,l2,l3;
    split2u(v.x,h0,l0); split2u(v.y,h1,l1); split2u(v.z,h2,l2); split2u(v.w,h3,l3);
    uint2 hh = make_uint2(pk2u(h0,h1), pk2u(h2,h3));
    uint2 ll = make_uint2(pk2u(l0,l1), pk2u(l2,l3));
    if (which < 3) {
        *(uint2*)(g_wch + (size_t)t*4) = hh;
        *(uint2*)(g_wcl + (size_t)t*4) = ll;
    } else {
        *(uint2*)(g_woh + (size_t)rem*4) = hh;
        *(uint2*)(g_wol + (size_t)rem*4) = ll;
    }
}

// ---------------- cosine sims (fp32, 64x32 tile, 256 blocks) ----------------
__global__ void k_sim(const float* __restrict__ x) {
    int b  = blockIdx.z;
    int a0 = blockIdx.y * 64;
    int b0 = blockIdx.x * 32;
    int tid = threadIdx.x;
    int tx = tid & 15, ty = tid >> 4;     // ty: 16 row-groups of 4; tx: 16 col-groups of 2
    __shared__ float As[16][68], Bs[16][36];
    const float* xb = x + (size_t)b * TT * DD;
    float acc[4][2];
    #pragma unroll
    for (int i = 0; i < 4; i++) { acc[i][0] = 0.f; acc[i][1] = 0.f; }

    int ar = tid >> 2, aq = tid & 3;
    for (int k0 = 0; k0 < DD; k0 += 16) {
        float4 va = *(const float4*)(xb + (size_t)(2*(a0+ar)) * DD + k0 + aq*4);
        As[aq*4+0][ar]=va.x; As[aq*4+1][ar]=va.y; As[aq*4+2][ar]=va.z; As[aq*4+3][ar]=va.w;
        if (tid < 128) {
            int br = tid >> 2, bq = tid & 3;
            float4 vb = *(const float4*)(xb + (size_t)(2*(b0+br)+1) * DD + k0 + bq*4);
            Bs[bq*4+0][br]=vb.x; Bs[bq*4+1][br]=vb.y; Bs[bq*4+2][br]=vb.z; Bs[bq*4+3][br]=vb.w;
        }
        __syncthreads();
        #pragma unroll
        for (int kk = 0; kk < 16; kk++) {
            float4 a4 = *(const float4*)&As[kk][ty*4];
            float2 b2 = *(const float2*)&Bs[kk][tx*2];
            acc[0][0] += a4.x*b2.x; acc[0][1] += a4.x*b2.y;
            acc[1][0] += a4.y*b2.x; acc[1][1] += a4.y*b2.y;
            acc[2][0] += a4.z*b2.x; acc[2][1] += a4.z*b2.y;
            acc[3][0] += a4.w*b2.x; acc[3][1] += a4.w*b2.y;
        }
        __syncthreads();
    }
    float ina[4], inb[2];
    #pragma unroll
    for (int i = 0; i < 4; i++) ina[i] = g_inorm[b*TT + 2*(a0+ty*4+i)];
    #pragma unroll
    for (int j = 0; j < 2; j++) inb[j] = g_inorm[b*TT + 2*(b0+tx*2+j) + 1];
    #pragma unroll
    for (int i = 0; i < 4; i++)
        #pragma unroll
        for (int j = 0; j < 2; j++) {
            float sim = acc[i][j] * ina[i] * inb[j];
            unsigned u = __float_as_uint(sim);
            u = (u & 0x80000000u) ? ~u : (u | 0x80000000u);
            int idx = (a0+ty*4+i) * TB2 + (b0+tx*2+j);
            g_keys[b*65536 + idx] = u;
            atomicAdd(&g_hist[b*NBINS + (u >> 18)], 1u);
        }
}

// ---------------- per-batch threshold bin ----------------
__global__ void k_thresh() {
    int b = blockIdx.x, t = threadIdx.x;
    __shared__ unsigned int csum[256];
    unsigned int s = 0;
    for (int j = 0; j < 64; j++) s += g_hist[b*NBINS + (NBINS-1 - (t*64 + j))];
    csum[t] = s;
    __syncthreads();
    if (t == 0) {
        unsigned int acc = 0; int thr = 0;
        int c = 0;
        for (; c < 256; c++) { if (acc + csum[c] >= TARGETN) break; acc += csum[c]; }
        if (c < 256) {
            int binBase = NBINS - 1 - c*64;
            for (int j = 0; j < 64; j++) {
                int bin = binBase - j;
                acc += g_hist[b*NBINS + bin];
                if (acc >= TARGETN) { thr = bin; break; }
            }
        }
        g_thr[b] = thr;
    }
}

// ---------------- gather top entries ----------------
__global__ void k_gather() {
    int i = blockIdx.x * blockDim.x + threadIdx.x;
    int b = i >> 16, idx = i & 65535;
    unsigned int key = g_keys[i];
    if ((int)(key >> 18) >= g_thr[b]) {
        int pos = atomicAdd(&g_cnt[b], 1);
        if (pos < CAP)
            g_gath[b*CAP + pos] =
                ((unsigned long long)key << 16) | (unsigned long long)(65535 - idx);
    }
}

// ---------------- bitonic sort + serial greedy + maps ----------------
__global__ void k_sortgreedy() {
    int b = blockIdx.x, tid = threadIdx.x;
    __shared__ unsigned long long S[CAP];
    __shared__ unsigned long long red[1024];
    __shared__ unsigned char ua[TA], ub[TB2];
    __shared__ int pa[RM], pb[RM];
    __shared__ int sm_cnt;

    int cnt = g_cnt[b];
    int lim = (cnt <= CAP) ? cnt : 0;
    for (int i = tid; i < CAP; i += 1024) S[i] = (i < lim) ? g_gath[b*CAP + i] : 0ULL;
    for (int i = tid; i < TA;  i += 1024) { ua[i] = 0; ub[i] = 0; }
    if (tid == 0) sm_cnt = 0;
    __syncthreads();

    for (int size = 2; size <= CAP; size <<= 1)
        for (int stride = size >> 1; stride > 0; stride >>= 1) {
            for (int t = tid; t < CAP/2; t += 1024) {
                int pos = 2*t - (t & (stride - 1));
                unsigned long long x0 = S[pos], x1 = S[pos + stride];
                bool up = ((pos & size) == 0);
                if (up ? (x0 < x1) : (x0 > x1)) { S[pos] = x1; S[pos + stride] = x0; }
            }
            __syncthreads();
        }

    if (tid == 0) {
        int m = 0;
        for (int i = 0; i < CAP && m < RM; i++) {
            unsigned long long e = S[i];
            if (!e) break;
            int idx = 65535 - (int)(e & 0xFFFFULL);
            int a = idx >> 8, bb = idx & 255;
            if (!ua[a] && !ub[bb]) { ua[a] = 1; ub[bb] = 1; pa[m] = a; pb[m] = bb; m++; }
        }
        sm_cnt = m;
    }
    __syncthreads();

    while (sm_cnt < RM) {
        unsigned long long best = 0ULL;
        for (int i = tid; i < 65536; i += 1024) {
            int a = i >> 8, bb = i & 255;
            if (ua[a] || ub[bb]) continue;
            unsigned long long comp =
                ((unsigned long long)g_keys[b*65536 + i] << 16) |
                (unsigned long long)(65535 - i);
            if (comp > best) best = comp;
        }
        red[tid] = best;
        __syncthreads();
        for (int o = 512; o; o >>= 1) {
            if (tid < o) { unsigned long long v = red[tid + o]; if (v > red[tid]) red[tid] = v; }
            __syncthreads();
        }
        if (tid == 0) {
            unsigned long long e = red[0];
            int idx = 65535 - (int)(e & 0xFFFFULL);
            int a = idx >> 8, bb = idx & 255;
            ua[a] = 1; ub[bb] = 1; pa[sm_cnt] = a; pb[sm_cnt] = bb; sm_cnt++;
        }
        __syncthreads();
    }

    if (tid == 0) {
        for (int a = 0; a < TA; a++) g_amap[b*TA + a] = -1;
        for (int i = 0; i < RM; i++) g_amap[b*TA + pa[i]] = pb[i];
        int k = 0;
        for (int bb = 0; bb < TB2; bb++)
            if (!ub[bb]) { g_kept[b*RM + k] = bb; g_bmap[b*TB2 + bb] = TA + k; k++; }
        for (int i = 0; i < RM; i++) g_bmap[b*TB2 + pb[i]] = pa[i];
    }
}

// ---------------- build merged tokens (writes bf16 hi/lo) ----------------
__global__ void k_merge(const float* __restrict__ x) {
    int b = blockIdx.y, row = blockIdx.x, tid = threadIdx.x;
    const float* xb = x + (size_t)b * TT * DD;
    float4 v;
    if (row < TA) {
        const float4* ra = (const float4*)(xb + (size_t)(2*row) * DD);
        int mb = g_amap[b*TA + row];
        if (mb >= 0) {
            const float4* rb = (const float4*)(xb + (size_t)(2*mb + 1) * DD);
            float4 va = ra[tid], vb = rb[tid];
            v = make_float4(0.5f*(va.x+vb.x), 0.5f*(va.y+vb.y),
                            0.5f*(va.z+vb.z), 0.5f*(va.w+vb.w));
        } else v = ra[tid];
    } else {
        int bb = g_kept[b*RM + row - TA];
        v = ((const float4*)(xb + (size_t)(2*bb + 1) * DD))[tid];
    }
    unsigned short h0,h1,h2,h3,l0,l1,l2,l3;
    split2u(v.x,h0,l0); split2u(v.y,h1,l1); split2u(v.z,h2,l2); split2u(v.w,h3,l3);
    size_t e = ((size_t)b*TMM + row) * DD + tid*4;
    *(uint2*)(g_mh + e) = make_uint2(pk2u(h0,h1), pk2u(h2,h3));
    *(uint2*)(g_ml + e) = make_uint2(pk2u(l0,l1), pk2u(l2,l3));
}

// =======================================================================
//  Pre-split bf16x3 tensor-core GEMM, cp.async double-buffered, ldmatrix.
// =======================================================================
#define BK 32
#define SROW 40
#define ARR_ELEMS (128*SROW)
#define STAGE_ELEMS (4*ARR_ELEMS)
#define SMEM_BYTES (2*STAGE_ELEMS*2)

#define MMA_BF16(d, a, b) \
    asm volatile("mma.sync.aligned.m16n8k16.row.col.f32.bf16.bf16.f32 " \
                 "{%0,%1,%2,%3},{%4,%5,%6,%7},{%8,%9},{%0,%1,%2,%3};" \
                 : "+f"(d[0]), "+f"(d[1]), "+f"(d[2]), "+f"(d[3]) \
                 : "r"(a[0]), "r"(a[1]), "r"(a[2]), "r"(a[3]), "r"(b[0]), "r"(b[1]))

__device__ __forceinline__ void cp16(unsigned short* dst, const unsigned short* src) {
    unsigned s = (unsigned)__cvta_generic_to_shared(dst);
    asm volatile("cp.async.cg.shared.global [%0], [%1], 16;\n" :: "r"(s), "l"(src));
}

// A-style x4: tiles (r0,kb),(r0+8,kb),(r0,kb+8),(r0+8,kb+8)
__device__ __forceinline__ void ldsmA(unsigned r[4], const unsigned short* base,
                                      int row0, int col0, int lane) {
    const unsigned short* p = base + (size_t)(row0 + ((lane>>3)&1)*8 + (lane&7))*SROW
                                   + col0 + ((lane>>4)&1)*8;
    unsigned a = (unsigned)__cvta_generic_to_shared(p);
    asm volatile("ldmatrix.sync.aligned.m8n8.x4.shared.b16 {%0,%1,%2,%3},[%4];"
                 : "=r"(r[0]), "=r"(r[1]), "=r"(r[2]), "=r"(r[3]) : "r"(a));
}
// B-style x4: tiles (n0,kb),(n0,kb+8),(n0+8,kb),(n0+8,kb+8)
__device__ __forceinline__ void ldsmB(unsigned r[4], const unsigned short* base,
                                      int row0, int col0, int lane) {
    const unsigned short* p = base + (size_t)(row0 + ((lane>>4)&1)*8 + (lane&7))*SROW
                                   + col0 + ((lane>>3)&1)*8;
    unsigned a = (unsigned)__cvta_generic_to_shared(p);
    asm volatile("ldmatrix.sync.aligned.m8n8.x4.shared.b16 {%0,%1,%2,%3},[%4];"
                 : "=r"(r[0]), "=r"(r[1]), "=r"(r[2]), "=r"(r[3]) : "r"(a));
}

__global__ __launch_bounds__(512)
void k_mma2(const unsigned short* __restrict__ Ahg, const unsigned short* __restrict__ Alg,
            const unsigned short* __restrict__ Bhg, const unsigned short* __restrict__ Blg,
            float* __restrict__ Cf, unsigned short* __restrict__ Ch, unsigned short* __restrict__ Cl,
            int M, int N, int K,
            long sAm, long sBn, long sBk, long sCm,
            long bAo, long bAi, long bBo, long bBi, long bCo, long bCi,
            int inner, float alpha, int modeB, int nlay)
{
    extern __shared__ unsigned short sm_[];
    int z = blockIdx.z, zo = z / inner, zi = z % inner;
    Ahg += (size_t)zo*bAo + (size_t)zi*bAi;
    Alg += (size_t)zo*bAo + (size_t)zi*bAi;
    Bhg += (size_t)zo*bBo + (size_t)zi*bBi;
    Blg += (size_t)zo*bBo + (size_t)zi*bBi;
    size_t coff = (size_t)zo*bCo + (size_t)zi*bCi;
    int m0 = blockIdx.y * 128, n0 = blockIdx.x * 128;

    int tid  = threadIdx.x;
    int warp = tid >> 5, lane = tid & 31;
    int g    = lane >> 2, tg = lane & 3;
    // layout 0: 4x4 warps, warp tile 32x32 (MT=2). layout 1: 8x2 warps, warp tile 16x32 (MT=1).
    int wm, wn, MT;
    if (!nlay) { wm = (warp >> 2) * 32; wn = (warp & 3) * 32; MT = 2; }
    else       { wm = (warp & 7) * 16;  wn = (warp >> 3) * 32; MT = 1; }

    float acc[2][4][4];
    #pragma unroll
    for (int i = 0; i < 2; i++)
        #pragma unroll
        for (int j = 0; j < 4; j++)
            #pragma unroll
            for (int c = 0; c < 4; c++) acc[i][j][c] = 0.f;

    const int ntiles = K / BK;

    auto fill = [&](int stage, int k0) {
        unsigned short* sb = sm_ + stage * STAGE_ELEMS;
        if (!modeB) {
            #pragma unroll
            for (int i = 0; i < 4; i++) {
                int c = tid + i*512;
                int arr = c >> 9, rem = c & 511;
                int row = rem >> 2, q = rem & 3;
                const unsigned short* src;
                if      (arr == 0) src = Ahg + (size_t)(m0+row)*sAm + k0 + q*8;
                else if (arr == 1) src = Alg + (size_t)(m0+row)*sAm + k0 + q*8;
                else if (arr == 2) src = Bhg + (size_t)(n0+row)*sBn + k0 + q*8;
                else               src = Blg + (size_t)(n0+row)*sBn + k0 + q*8;
                cp16(sb + arr*ARR_ELEMS + row*SROW + q*8, src);
            }
        } else {
            #pragma unroll
            for (int i = 0; i < 2; i++) {
                int c = tid + i*512;
                int arr = c >> 9, rem = c & 511;
                int row = rem >> 2, q = rem & 3;
                const unsigned short* src = (arr ? Alg : Ahg) + (size_t)(m0+row)*sAm + k0 + q*8;
                cp16(sb + arr*ARR_ELEMS + row*SROW + q*8, src);
            }
            #pragma unroll
            for (int i = 0; i < 8; i++) {
                int s = tid + i*512;
                int n = s & 127, kk = s >> 7;
                int gn = n0 + n;
                if (gn < N) {
                    size_t off = (size_t)gn + (size_t)(k0 + kk) * sBk;
                    sb[2*ARR_ELEMS + n*SROW + kk] = Bhg[off];
                    sb[3*ARR_ELEMS + n*SROW + kk] = Blg[off];
                }
                // rows n >= N are never read by the nlay=1 warp layout; skip writes
            }
        }
    };

    fill(0, 0);
    asm volatile("cp.async.commit_group;\n");

    for (int t = 0; t < ntiles; t++) {
        if (t + 1 < ntiles) fill((t+1) & 1, (t+1)*BK);
        asm volatile("cp.async.commit_group;\n");
        asm volatile("cp.async.wait_group 1;\n");
        __syncthreads();

        const unsigned short* sb = sm_ + (t & 1) * STAGE_ELEMS;
        const unsigned short* Ahs = sb;
        const unsigned short* Als = sb + ARR_ELEMS;
        const unsigned short* Bhs = sb + 2*ARR_ELEMS;
        const unsigned short* Bls = sb + 3*ARR_ELEMS;

        #pragma unroll
        for (int kc = 0; kc < 2; kc++) {
            int kb = kc*16;
            unsigned ah[2][4], al[2][4], bh[4][2], bl[4][2];
            #pragma unroll
            for (int mt = 0; mt < 2; mt++) {
                if (mt < MT) {
                    ldsmA(ah[mt], Ahs, wm + mt*16, kb, lane);
                    ldsmA(al[mt], Als, wm + mt*16, kb, lane);
                }
            }
            {
                unsigned tmp[4];
                ldsmB(tmp, Bhs, wn, kb, lane);
                bh[0][0]=tmp[0]; bh[0][1]=tmp[1]; bh[1][0]=tmp[2]; bh[1][1]=tmp[3];
                ldsmB(tmp, Bhs, wn + 16, kb, lane);
                bh[2][0]=tmp[0]; bh[2][1]=tmp[1]; bh[3][0]=tmp[2]; bh[3][1]=tmp[3];
                ldsmB(tmp, Bls, wn, kb, lane);
                bl[0][0]=tmp[0]; bl[0][1]=tmp[1]; bl[1][0]=tmp[2]; bl[1][1]=tmp[3];
                ldsmB(tmp, Bls, wn + 16, kb, lane);
                bl[2][0]=tmp[0]; bl[2][1]=tmp[1]; bl[3][0]=tmp[2]; bl[3][1]=tmp[3];
            }
            #pragma unroll
            for (int mt = 0; mt < 2; mt++) if (mt < MT)
                #pragma unroll
                for (int nt = 0; nt < 4; nt++) MMA_BF16(acc[mt][nt], ah[mt], bh[nt]);
            #pragma unroll
            for (int mt = 0; mt < 2; mt++) if (mt < MT)
                #pragma unroll
                for (int nt = 0; nt < 4; nt++) MMA_BF16(acc[mt][nt], ah[mt], bl[nt]);
            #pragma unroll
            for (int mt = 0; mt < 2; mt++) if (mt < MT)
                #pragma unroll
                for (int nt = 0; nt < 4; nt++) MMA_BF16(acc[mt][nt], al[mt], bh[nt]);
        }
        __syncthreads();
    }

    // ---- epilogue ----
    #pragma unroll
    for (int mt = 0; mt < 2; mt++) {
        if (mt >= MT) continue;
        #pragma unroll
        for (int nt = 0; nt < 4; nt++) {
            int gm = m0 + wm + mt*16 + g;
            int gn = n0 + wn + nt*8 + 2*tg;
            if (gn >= N) continue;
            float v0 = alpha*acc[mt][nt][0], v1 = alpha*acc[mt][nt][1];
            float v2 = alpha*acc[mt][nt][2], v3 = alpha*acc[mt][nt][3];
            if (Cf) {
                if (gm < M)     *(float2*)(Cf + coff + (size_t)gm*sCm + gn)     = make_float2(v0, v1);
                if (gm + 8 < M) *(float2*)(Cf + coff + (size_t)(gm+8)*sCm + gn) = make_float2(v2, v3);
            }
            if (Ch) {
                unsigned short h0,h1,h2,h3,l0,l1,l2,l3;
                split2u(v0,h0,l0); split2u(v1,h1,l1); split2u(v2,h2,l2); split2u(v3,h3,l3);
                if (gm < M) {
                    *(unsigned*)(Ch + coff + (size_t)gm*sCm + gn) = pk2u(h0,h1);
                    *(unsigned*)(Cl + coff + (size_t)gm*sCm + gn) = pk2u(l0,l1);
                }
                if (gm + 8 < M) {
                    *(unsigned*)(Ch + coff + (size_t)(gm+8)*sCm + gn) = pk2u(h2,h3);
                    *(unsigned*)(Cl + coff + (size_t)(gm+8)*sCm + gn) = pk2u(l2,l3);
                }
            }
        }
    }
}

// ---------------- softmax over rows of 384 ----------------
__global__ void k_softmax() {
    int row = blockIdx.x, tid = threadIdx.x;
    float* p = g_s + (size_t)row * TMM;
    float v0 = p[tid], v1 = p[tid + 128], v2 = p[tid + 256];
    float mx = fmaxf(v0, fmaxf(v1, v2));
    __shared__ float sw[4], sw2[4];
    #pragma unroll
    for (int o = 16; o; o >>= 1) mx = fmaxf(mx, __shfl_xor_sync(0xffffffffu, mx, o));
    if ((tid & 31) == 0) sw[tid >> 5] = mx;
    __syncthreads();
    mx = fmaxf(fmaxf(sw[0], sw[1]), fmaxf(sw[2], sw[3]));
    v0 = expf(v0 - mx); v1 = expf(v1 - mx); v2 = expf(v2 - mx);
    float s = v0 + v1 + v2;
    #pragma unroll
    for (int o = 16; o; o >>= 1) s += __shfl_xor_sync(0xffffffffu, s, o);
    if ((tid & 31) == 0) sw2[tid >> 5] = s;
    __syncthreads();
    s = sw2[0] + sw2[1] + sw2[2] + sw2[3];
    float inv = 1.0f / s;
    size_t base = (size_t)row * TMM;
    unsigned short h, l;
    split2u(v0*inv, h, l); g_ph[base + tid]       = h; g_pl[base + tid]       = l;
    split2u(v1*inv, h, l); g_ph[base + tid + 128] = h; g_pl[base + tid + 128] = l;
    split2u(v2*inv, h, l); g_ph[base + tid + 256] = h; g_pl[base + tid + 256] = l;
}

// ---------------- unmerge into output ----------------
__global__ void k_unmerge(float* __restrict__ out) {
    int b = blockIdx.y, t = blockIdx.x, tid = threadIdx.x;
    int src = (t & 1) ? g_bmap[b*TB2 + (t >> 1)] : (t >> 1);
    const float4* s = (const float4*)(g_pr + ((size_t)b*TMM + src) * DD);
    float4* d = (float4*)(out + ((size_t)b*TT + t) * DD);
    d[tid] = s[tid];
}

// ---------------- launch ----------------
extern "C" void kernel_launch(void* const* d_in, const int* in_sizes, int n_in,
                              void* d_out, int out_size) {
    (void)in_sizes; (void)n_in; (void)out_size;
    const float* x  = (const float*)d_in[0];
    const float* Wq = (const float*)d_in[1];
    const float* Wk = (const float*)d_in[2];
    const float* Wv = (const float*)d_in[3];
    const float* Wo = (const float*)d_in[4];
    float* out = (float*)d_out;

    static int smem_set = 0;
    if (!smem_set) {
        cudaFuncSetAttribute(k_mma2, cudaFuncAttributeMaxDynamicSharedMemorySize, SMEM_BYTES);
        smem_set = 1;
    }

    unsigned short *pmh,*pml,*pwch,*pwcl,*pwoh,*pwol,*pqkh,*pqkl,*pph,*ppl,*paoh,*paol;
    float *ps, *ppr;
    cudaGetSymbolAddress((void**)&pmh,  g_mh);  cudaGetSymbolAddress((void**)&pml,  g_ml);
    cudaGetSymbolAddress((void**)&pwch, g_wch); cudaGetSymbolAddress((void**)&pwcl, g_wcl);
    cudaGetSymbolAddress((void**)&pwoh, g_woh); cudaGetSymbolAddress((void**)&pwol, g_wol);
    cudaGetSymbolAddress((void**)&pqkh, g_qkh); cudaGetSymbolAddress((void**)&pqkl, g_qkl);
    cudaGetSymbolAddress((void**)&pph,  g_ph);  cudaGetSymbolAddress((void**)&ppl,  g_pl);
    cudaGetSymbolAddress((void**)&paoh, g_aoh); cudaGetSymbolAddress((void**)&paol, g_aol);
    cudaGetSymbolAddress((void**)&ps,   g_s);   cudaGetSymbolAddress((void**)&ppr,  g_pr);

    k_init<<<(NB*NBINS + 255)/256, 256>>>();
    k_norm<<<NB*TT/8, 256>>>(x);
    k_cvtW<<<4096, 256>>>(Wq, Wk, Wv, Wo);
    k_sim<<<dim3(8, 4, NB), 256>>>(x);
    k_thresh<<<NB, 256>>>();
    k_gather<<<512, 1024>>>();
    k_sortgreedy<<<NB, 1024>>>();
    k_merge<<<dim3(TMM, NB), 256>>>(x);

    const long MD3 = (long)TMM * 3 * DD;

    // fused QKV projection: (3072 x 3072) = merged(3072x1024) @ Wcat^T -> split bf16
    k_mma2<<<dim3(24, 24, 1), 512, SMEM_BYTES>>>(
        pmh, pml, pwch, pwcl, nullptr, pqkh, pqkl,
        NB*TMM, 3*DD, DD,
        DD, DD, 0, 3*DD,
        0,0, 0,0, 0,0, 1, 1.0f, 0, 0);

    // scores: per (b,h): (384x384) = Q_bh @ K_bh^T / 8  -> fp32
    k_mma2<<<dim3(3, 3, NB*NH), 512, SMEM_BYTES>>>(
        pqkh, pqkl, pqkh + DD, pqkl + DD, ps, nullptr, nullptr,
        TMM, TMM, HD,
        3*DD, 3*DD, 0, TMM,
        MD3, (long)HD, MD3, (long)HD, (long)NH*SS, (long)SS, NH, 0.125f, 0, 0);

    k_softmax<<<NB*NH*TMM, 128>>>();

    // attn @ V: per (b,h): (384x64) = P @ V_bh  (nlay=1: 8x2 warp layout, exact 128x64)
    k_mma2<<<dim3(1, 3, NB*NH), 512, SMEM_BYTES>>>(
        pph, ppl, pqkh + 2*DD, pqkl + 2*DD, nullptr, paoh, paol,
        TMM, HD, TMM,
        TMM, 0, 3*DD, DD,
        (long)NH*SS, (long)SS, MD3, (long)HD, (long)TMM*DD, (long)HD, NH, 1.0f, 1, 1);

    // output projection -> fp32
    k_mma2<<<dim3(8, 24, 1), 512, SMEM_BYTES>>>(
        paoh, paol, pwoh, pwol, ppr, nullptr, nullptr,
        NB*TMM, DD, DD,
        DD, DD, 0, DD,
        0,0, 0,0, 0,0, 1, 1.0f, 0, 0);

    k_unmerge<<<dim3(TT, NB), 256>>>(out);
}